// round 1
// baseline (speedup 1.0000x reference)
#include <cuda_runtime.h>
#include <cuda_bf16.h>
#include <math.h>
#include <stdint.h>

#define B_    2
#define T_    1024
#define BT_   2048
#define DIM_  2048
#define NH_   16
#define DH_   128
#define DRH_  64
#define DC_   512
#define NE_   16
#define TOPK_ 4
#define MOE_  1024
#define MOESH_ 2048
#define CAP_  2048
#define QKD_  192   // DH + DRH

// ---------------- scratch (static device globals; no runtime alloc) ----------
__device__ float g_h  [BT_*DIM_];
__device__ float g_ckv[BT_*DC_];
__device__ float g_cq [BT_*DC_];
__device__ float g_Q  [BT_*NH_*QKD_];
__device__ float g_K  [BT_*NH_*QKD_];
__device__ float g_V  [BT_*NH_*DH_];
__device__ float g_kr [BT_*DRH_];
__device__ float g_S  [(size_t)B_*NH_*T_*T_];
__device__ float g_O  [BT_*NH_*DH_];
__device__ float g_Wo [DIM_*NH_*DH_];
__device__ float g_x1 [BT_*DIM_];
__device__ float g_xn [BT_*DIM_];
__device__ float g_a1 [BT_*MOESH_];
__device__ float g_a3 [BT_*MOESH_];
__device__ float g_h1 [(size_t)NE_*CAP_*MOE_];
__device__ float g_h2 [(size_t)NE_*CAP_*MOE_];
__device__ int   g_cnt[NE_];
__device__ int   g_tok[NE_*CAP_];
__device__ float g_wt [NE_*CAP_];

// ---------------- generic fp32 GEMM ------------------------------------------
// MODE 0: C = A(M,K) * B(K,N)      (NN)
// MODE 1: C = A(M,K) * B(N,K)^T    (NT)
// MODE 2: C = A(K,M)^T * B(K,N)    (TN)
struct GemmP {
    const float* A; const float* B; float* C; const float* res;
    int M, N, K, lda, ldb, ldc;
    float alpha;
    long long aO1, aO2, bO1, bO2, cO1, cO2;
    int zdiv, cap;
    const int* Mvec;    // per-z dynamic M (row count)
    const int* aRows;   // per-z row gather indices into A
    const int* cRows;   // per-z row scatter indices into C (atomicAdd)
    const float* wRow;  // per-row scatter weight
};

template<int MODE>
__global__ __launch_bounds__(256) void gemm_k(GemmP p) {
    __shared__ float As[8][128];
    __shared__ float Bs[8][128];
    int z = blockIdx.z, z1 = z / p.zdiv, z2 = z - z1 * p.zdiv;
    const float* A  = p.A + z1 * p.aO1 + z2 * p.aO2;
    const float* Bp = p.B + z1 * p.bO1 + z2 * p.bO2;
    float*       C  = p.C + z1 * p.cO1 + z2 * p.cO2;
    int M = p.Mvec ? p.Mvec[z] : p.M;
    int m0 = blockIdx.y * 128, n0 = blockIdx.x * 128;
    if (m0 >= M) return;
    int tid = threadIdx.x;

    float acc[8][8];
#pragma unroll
    for (int i = 0; i < 8; i++)
#pragma unroll
        for (int j = 0; j < 8; j++) acc[i][j] = 0.f;

    int r2 = tid >> 1, vi = tid & 1;
    int kk5 = tid >> 5, c4 = (tid & 31) << 2;

    long long arowbase = 0;
    if (MODE != 2) {
        int row = m0 + r2; if (row > M - 1) row = M - 1;
        long long ar = p.aRows ? (long long)p.aRows[(long long)z * p.cap + row]
                               : (long long)row;
        arowbase = ar * (long long)p.lda + vi * 4;
    }
    long long bcolbase = 0;
    if (MODE == 1) {
        int col = n0 + r2; if (col > p.N - 1) col = p.N - 1;
        bcolbase = (long long)col * p.ldb + vi * 4;
    }
    int nIdx = n0 + c4;
    if (MODE != 1) { if (nIdx > p.N - 4) nIdx = p.N - 4; }

    for (int k0 = 0; k0 < p.K; k0 += 8) {
        if (MODE == 2) {
            float4 v = *(const float4*)(A + (long long)(k0 + kk5) * p.lda + m0 + c4);
            *(float4*)&As[kk5][c4] = v;
        } else {
            float4 v = *(const float4*)(A + arowbase + k0);
            As[vi*4+0][r2] = v.x; As[vi*4+1][r2] = v.y;
            As[vi*4+2][r2] = v.z; As[vi*4+3][r2] = v.w;
        }
        if (MODE == 1) {
            float4 v = *(const float4*)(Bp + bcolbase + k0);
            Bs[vi*4+0][r2] = v.x; Bs[vi*4+1][r2] = v.y;
            Bs[vi*4+2][r2] = v.z; Bs[vi*4+3][r2] = v.w;
        } else {
            float4 v = *(const float4*)(Bp + (long long)(k0 + kk5) * p.ldb + nIdx);
            *(float4*)&Bs[kk5][c4] = v;
        }
        __syncthreads();
        int ty = tid >> 4, tx = tid & 15;
#pragma unroll
        for (int kk = 0; kk < 8; kk++) {
            float a[8], b[8];
            *(float4*)&a[0] = *(const float4*)&As[kk][ty*8];
            *(float4*)&a[4] = *(const float4*)&As[kk][ty*8+4];
            *(float4*)&b[0] = *(const float4*)&Bs[kk][tx*8];
            *(float4*)&b[4] = *(const float4*)&Bs[kk][tx*8+4];
#pragma unroll
            for (int i = 0; i < 8; i++)
#pragma unroll
                for (int j = 0; j < 8; j++)
                    acc[i][j] = fmaf(a[i], b[j], acc[i][j]);
        }
        __syncthreads();
    }

    int ty = tid >> 4, tx = tid & 15;
#pragma unroll
    for (int i = 0; i < 8; i++) {
        int m = m0 + ty * 8 + i;
        if (m >= M) continue;
        long long crow; float w = p.alpha;
        if (p.cRows) {
            crow = (long long)p.cRows[(long long)z * p.cap + m] * p.ldc;
            w *= p.wRow[(long long)z * p.cap + m];
        } else {
            crow = (long long)m * p.ldc;
        }
#pragma unroll
        for (int j = 0; j < 8; j++) {
            int n = n0 + tx * 8 + j;
            if (n >= p.N) continue;
            float v = acc[i][j] * w;
            if (p.cRows) atomicAdd(&C[crow + n], v);
            else { if (p.res) v += p.res[crow + n]; C[crow + n] = v; }
        }
    }
}

// ---------------- small fused kernels -----------------------------------------
__global__ void rmsnorm_k(const float* __restrict__ x, const float* __restrict__ w,
                          float* __restrict__ o) {
    int r = blockIdx.x;
    const float* xr = x + (long long)r * DIM_;
    float s = 0.f;
    for (int d = threadIdx.x; d < DIM_; d += 256) { float v = xr[d]; s += v * v; }
    __shared__ float red[256];
    red[threadIdx.x] = s; __syncthreads();
    for (int off = 128; off; off >>= 1) {
        if (threadIdx.x < off) red[threadIdx.x] += red[threadIdx.x + off];
        __syncthreads();
    }
    float inv = rsqrtf(red[0] / (float)DIM_ + 1e-6f);
    float* orow = o + (long long)r * DIM_;
    for (int d = threadIdx.x; d < DIM_; d += 256) orow[d] = w[d] * xr[d] * inv;
}

__device__ __forceinline__ void rope_cs(int t, int j, float& c, float& s) {
    float freq = 1.0f / powf(10000.0f, (float)(2 * j) / (float)DRH_);
    float ang = (float)t * freq;
    sincosf(ang, &s, &c);
}

__global__ void rope_q_k(float* __restrict__ Q) {
    int idx = blockIdx.x;            // bt*NH + h
    int bt = idx / NH_;
    int t = bt % T_;
    int j = threadIdx.x;             // 0..31
    float* base = Q + (long long)idx * QKD_ + DH_;
    float re = base[j], im = base[32 + j];
    float c, s; rope_cs(t, j, c, s);
    base[j]      = re * c - im * s;
    base[32 + j] = re * s + im * c;
}

__global__ void rope_kr_k(const float* __restrict__ kr, float* __restrict__ Kb) {
    int bt = blockIdx.x;
    int t = bt % T_;
    int j = threadIdx.x;             // 0..31
    float re = kr[bt * DRH_ + j], im = kr[bt * DRH_ + 32 + j];
    float c, s; rope_cs(t, j, c, s);
    float o1 = (re * c - im * s) / (float)NH_;
    float o2 = (re * s + im * c) / (float)NH_;
    for (int h = 0; h < NH_; h++) {
        float* base = Kb + ((long long)bt * NH_ + h) * QKD_ + DH_;
        base[j] = o1; base[32 + j] = o2;
    }
}

__global__ void softmax_k(float* __restrict__ S) {
    long long r = blockIdx.x;        // (b,h,t) row
    int t = (int)(r & (T_ - 1));
    float* row = S + r * (long long)T_;
    int n = t + 1;
    __shared__ float red[256];
    int tid = threadIdx.x;
    float mx = -INFINITY;
    for (int l = tid; l < n; l += 256) mx = fmaxf(mx, row[l]);
    red[tid] = mx; __syncthreads();
    for (int off = 128; off; off >>= 1) {
        if (tid < off) red[tid] = fmaxf(red[tid], red[tid + off]);
        __syncthreads();
    }
    mx = red[0]; __syncthreads();
    float sum = 0.f;
    for (int l = tid; l < n; l += 256) { float e = expf(row[l] - mx); row[l] = e; sum += e; }
    red[tid] = sum; __syncthreads();
    for (int off = 128; off; off >>= 1) {
        if (tid < off) red[tid] += red[tid + off];
        __syncthreads();
    }
    float inv = 1.f / red[0];
    for (int l = tid; l < T_; l += 256) row[l] = (l < n) ? row[l] * inv : 0.f;
}

__global__ void pack_wo_k(const float* __restrict__ wo, float* __restrict__ out) {
    long long i = (long long)blockIdx.x * 256 + threadIdx.x;  // d*2048 + h*128 + k
    if (i >= (long long)DIM_ * 2048) return;
    int d = (int)(i >> 11);
    int r = (int)(i & 2047);
    int h = r >> 7, k = r & 127;
    out[i] = wo[(long long)d * 2048 + k * NH_ + h];
}

__global__ void gate_k(const float* __restrict__ xn, const float* __restrict__ gw,
                       const float* __restrict__ gb, float* affOut,
                       int* __restrict__ cnt, int* __restrict__ tok,
                       float* __restrict__ wt) {
    int bt = blockIdx.x;
    __shared__ float xrow[DIM_];
    __shared__ float aff[NE_];
    int tid = threadIdx.x;
    for (int d = tid; d < DIM_; d += 256) xrow[d] = xn[(long long)bt * DIM_ + d];
    __syncthreads();
    int w = tid >> 5, lane = tid & 31;
    for (int e = w; e < NE_; e += 8) {
        float s = 0.f;
        const float* gr = gw + (long long)e * DIM_;
        for (int d = lane; d < DIM_; d += 32) s += xrow[d] * gr[d];
        for (int o = 16; o; o >>= 1) s += __shfl_xor_sync(0xffffffffu, s, o);
        if (lane == 0) aff[e] = 1.f / (1.f + expf(-s)) + gb[e];
    }
    __syncthreads();
    if (tid == 0) {
        if (affOut) for (int e = 0; e < NE_; e++) affOut[(long long)bt * NE_ + e] = aff[e];
        bool used[NE_] = {};
        float wv[TOPK_]; int wi[TOPK_]; float sum = 0.f;
        for (int k = 0; k < TOPK_; k++) {
            float best = -1e30f; int bi = 0;
            for (int e = 0; e < NE_; e++)
                if (!used[e] && aff[e] > best) { best = aff[e]; bi = e; }
            used[bi] = true; wv[k] = best; wi[k] = bi; sum += best;
        }
        for (int k = 0; k < TOPK_; k++) {
            int e = wi[k];
            int pos = atomicAdd(&cnt[e], 1);
            tok[e * CAP_ + pos] = bt;
            wt [e * CAP_ + pos] = wv[k] / sum;
        }
    }
}

__global__ void silumul_k(float* __restrict__ a, const float* __restrict__ b, long long n) {
    long long i = (long long)blockIdx.x * 256 + threadIdx.x;
    if (i < n) { float z = a[i] * b[i]; a[i] = z / (1.f + expf(-z)); }
}

__global__ void silumul_routed_k(float* __restrict__ a, const float* __restrict__ b,
                                 const int* __restrict__ cnt) {
    long long i = (long long)blockIdx.x * 256 + threadIdx.x;   // NE*CAP*MOE
    int e = (int)(i >> 21);                // CAP_*MOE_ = 2^21
    int ri = (int)((i >> 10) & (CAP_ - 1));
    if (ri >= cnt[e]) return;
    float z = a[i] * b[i];
    a[i] = z / (1.f + expf(-z));
}

// ---------------- host-side launch helpers ------------------------------------
template<int MODE>
static void gemm(const float* A, const float* B, float* C, int M, int N, int K,
                 int lda, int ldb, int ldc, float alpha, const float* res,
                 int nz, int zdiv,
                 long long a1, long long a2, long long b1, long long b2,
                 long long c1, long long c2,
                 const int* Mvec = nullptr, const int* aRows = nullptr,
                 const int* cRows = nullptr, const float* wRow = nullptr,
                 int cap = 0) {
    GemmP p;
    p.A = A; p.B = B; p.C = C; p.res = res;
    p.M = M; p.N = N; p.K = K; p.lda = lda; p.ldb = ldb; p.ldc = ldc;
    p.alpha = alpha;
    p.aO1 = a1; p.aO2 = a2; p.bO1 = b1; p.bO2 = b2; p.cO1 = c1; p.cO2 = c2;
    p.zdiv = zdiv; p.cap = cap;
    p.Mvec = Mvec; p.aRows = aRows; p.cRows = cRows; p.wRow = wRow;
    dim3 g((N + 127) / 128, (M + 127) / 128, nz);
    gemm_k<MODE><<<g, 256>>>(p);
}

extern "C" void kernel_launch(void* const* d_in, const int* in_sizes, int n_in,
                              void* d_out, int out_size) {
    const float* x      = (const float*)d_in[0];
    const float* attn_w = (const float*)d_in[3];
    const float* ffn_w  = (const float*)d_in[4];
    const float* gate_w = (const float*)d_in[5];
    const float* gate_b = (const float*)d_in[6];
    const float* w1s    = (const float*)d_in[7];
    const float* w2s    = (const float*)d_in[8];
    const float* w3s    = (const float*)d_in[9];
    const float* w1r    = (const float*)d_in[10];
    const float* w2r    = (const float*)d_in[11];
    const float* w3r    = (const float*)d_in[12];
    const float* wdkv   = (const float*)d_in[13];
    const float* wuk    = (const float*)d_in[14];
    const float* wuv    = (const float*)d_in[15];
    const float* wdq    = (const float*)d_in[16];
    const float* wuq    = (const float*)d_in[17];
    const float* wqr    = (const float*)d_in[18];
    const float* wkr    = (const float*)d_in[19];
    const float* wo     = (const float*)d_in[20];
    float* out = (float*)d_out;

    float *h, *ckv, *cq, *Q, *K, *V, *kr, *S, *O, *Wo, *x1, *xn, *a1, *a3, *h1, *h2, *wt;
    int *cnt, *tok;
    cudaGetSymbolAddress((void**)&h,   g_h);
    cudaGetSymbolAddress((void**)&ckv, g_ckv);
    cudaGetSymbolAddress((void**)&cq,  g_cq);
    cudaGetSymbolAddress((void**)&Q,   g_Q);
    cudaGetSymbolAddress((void**)&K,   g_K);
    cudaGetSymbolAddress((void**)&V,   g_V);
    cudaGetSymbolAddress((void**)&kr,  g_kr);
    cudaGetSymbolAddress((void**)&S,   g_S);
    cudaGetSymbolAddress((void**)&O,   g_O);
    cudaGetSymbolAddress((void**)&Wo,  g_Wo);
    cudaGetSymbolAddress((void**)&x1,  g_x1);
    cudaGetSymbolAddress((void**)&xn,  g_xn);
    cudaGetSymbolAddress((void**)&a1,  g_a1);
    cudaGetSymbolAddress((void**)&a3,  g_a3);
    cudaGetSymbolAddress((void**)&h1,  g_h1);
    cudaGetSymbolAddress((void**)&h2,  g_h2);
    cudaGetSymbolAddress((void**)&cnt, g_cnt);
    cudaGetSymbolAddress((void**)&tok, g_tok);
    cudaGetSymbolAddress((void**)&wt,  g_wt);

    // ---- attention ----
    rmsnorm_k<<<BT_, 256>>>(x, attn_w, h);
    // c_kv, c_q : (BT,DIM) x (DC,DIM)^T
    gemm<1>(h, wdkv, ckv, BT_, DC_, DIM_, DIM_, DIM_, DC_, 1.f, nullptr, 1, 1, 0,0,0,0,0,0);
    gemm<1>(h, wdq,  cq,  BT_, DC_, DIM_, DIM_, DIM_, DC_, 1.f, nullptr, 1, 1, 0,0,0,0,0,0);
    // per-head up-projections (batched over h; weight row stride NH*DC, sub-offset h*DC)
    gemm<1>(ckv, wuk, K,       BT_, DH_,  DC_, DC_, NH_*DC_, NH_*QKD_, 1.f, nullptr,
            NH_, NH_, 0,0, 0, DC_, 0, QKD_);
    gemm<1>(ckv, wuv, V,       BT_, DH_,  DC_, DC_, NH_*DC_, NH_*DH_,  1.f, nullptr,
            NH_, NH_, 0,0, 0, DC_, 0, DH_);
    gemm<1>(cq,  wuq, Q,       BT_, DH_,  DC_, DC_, NH_*DC_, NH_*QKD_, 1.f, nullptr,
            NH_, NH_, 0,0, 0, DC_, 0, QKD_);
    gemm<1>(cq,  wqr, Q + DH_, BT_, DRH_, DC_, DC_, NH_*DC_, NH_*QKD_, 1.f, nullptr,
            NH_, NH_, 0,0, 0, DC_, 0, QKD_);
    // k_r = h @ w_kr^T
    gemm<1>(h, wkr, kr, BT_, DRH_, DIM_, DIM_, DIM_, DRH_, 1.f, nullptr, 1, 1, 0,0,0,0,0,0);
    rope_q_k<<<BT_ * NH_, 32>>>(Q);
    rope_kr_k<<<BT_, 32>>>(kr, K);
    // logits (batched over b,h), scaled
    float scale = 1.0f / sqrtf((float)QKD_);
    gemm<1>(Q, K, S, T_, T_, QKD_, NH_*QKD_, NH_*QKD_, T_, scale, nullptr,
            B_*NH_, NH_,
            (long long)T_*NH_*QKD_, QKD_,
            (long long)T_*NH_*QKD_, QKD_,
            (long long)NH_*T_*T_, (long long)T_*T_);
    softmax_k<<<B_ * NH_ * T_, 256>>>(S);
    // out[l,k] = sum_t S[t,l] V[t,k]  (TN)
    gemm<2>(S, V, O, T_, DH_, T_, T_, NH_*DH_, NH_*DH_, 1.f, nullptr,
            B_*NH_, NH_,
            (long long)NH_*T_*T_, (long long)T_*T_,
            (long long)T_*NH_*DH_, DH_,
            (long long)T_*NH_*DH_, DH_);
    // attn projection + residual
    pack_wo_k<<<(DIM_*2048 + 255)/256, 256>>>(wo, Wo);
    gemm<1>(O, Wo, x1, BT_, DIM_, NH_*DH_, NH_*DH_, NH_*DH_, DIM_, 1.f, x,
            1, 1, 0,0,0,0,0,0);

    // ---- MoE ----
    rmsnorm_k<<<BT_, 256>>>(x1, ffn_w, xn);
    cudaMemsetAsync(cnt, 0, NE_ * sizeof(int));
    float* affOut = (out_size >= BT_*DIM_ + BT_*NE_) ? out + (long long)BT_*DIM_ : nullptr;
    gate_k<<<BT_, 256>>>(xn, gate_w, gate_b, affOut, cnt, tok, wt);
    // shared expert
    gemm<0>(xn, w1s, a1, BT_, MOESH_, DIM_, DIM_, MOESH_, MOESH_, 1.f, nullptr, 1,1,0,0,0,0,0,0);
    gemm<0>(xn, w3s, a3, BT_, MOESH_, DIM_, DIM_, MOESH_, MOESH_, 1.f, nullptr, 1,1,0,0,0,0,0,0);
    silumul_k<<<(BT_*MOESH_ + 255)/256, 256>>>(a1, a3, (long long)BT_*MOESH_);
    gemm<0>(a1, w2s, out, BT_, DIM_, MOESH_, MOESH_, DIM_, DIM_, 1.f, x1, 1,1,0,0,0,0,0,0);
    // routed experts (top-4 only; gathered GEMMs with dynamic M, fused weighted scatter)
    gemm<0>(xn, w1r, h1, CAP_, MOE_, DIM_, DIM_, MOE_, MOE_, 1.f, nullptr,
            NE_, NE_, 0,0, 0, (long long)DIM_*MOE_, 0, (long long)CAP_*MOE_,
            cnt, tok, nullptr, nullptr, CAP_);
    gemm<0>(xn, w3r, h2, CAP_, MOE_, DIM_, DIM_, MOE_, MOE_, 1.f, nullptr,
            NE_, NE_, 0,0, 0, (long long)DIM_*MOE_, 0, (long long)CAP_*MOE_,
            cnt, tok, nullptr, nullptr, CAP_);
    silumul_routed_k<<<((long long)NE_*CAP_*MOE_ + 255)/256, 256>>>(h1, h2, cnt);
    gemm<0>(h1, w2r, out, CAP_, DIM_, MOE_, MOE_, DIM_, DIM_, 1.f, nullptr,
            NE_, NE_, 0, (long long)CAP_*MOE_, 0, (long long)MOE_*DIM_, 0, 0,
            cnt, nullptr, tok, wt, CAP_);
}

// round 4
// speedup vs baseline: 1.1899x; 1.1899x over previous
#include <cuda_runtime.h>
#include <cuda_bf16.h>
#include <math.h>
#include <stdint.h>

#define B_    2
#define T_    1024
#define BT_   2048
#define DIM_  2048
#define NH_   16
#define DH_   128
#define DRH_  64
#define DC_   512
#define NE_   16
#define TOPK_ 4
#define MOE_  1024
#define MOESH_ 2048
#define CAP_  2048
#define QKD_  192   // DH + DRH

// ---------------- scratch (static device globals; no runtime alloc) ----------
__device__ float g_h  [BT_*DIM_];
__device__ float g_ckv[BT_*DC_];
__device__ float g_cq [BT_*DC_];
__device__ float g_Q  [BT_*NH_*QKD_];
__device__ float g_K  [BT_*NH_*QKD_];
__device__ float g_V  [BT_*NH_*DH_];
__device__ float g_kr [BT_*DRH_];
__device__ float g_S  [(size_t)B_*NH_*T_*T_];
__device__ float g_O  [BT_*NH_*DH_];
__device__ float g_Wo [DIM_*NH_*DH_];
__device__ float g_x1 [BT_*DIM_];
__device__ float g_xn [BT_*DIM_];
__device__ float g_a1 [BT_*MOESH_];
__device__ float g_a3 [BT_*MOESH_];
__device__ float g_h1 [(size_t)NE_*CAP_*MOE_];
__device__ float g_h2 [(size_t)NE_*CAP_*MOE_];
__device__ int   g_cnt[NE_];
__device__ int   g_tok[NE_*CAP_];
__device__ float g_wt [NE_*CAP_];

// ---------------- 3xTF32 tensor-core GEMM (single-buffer, zero-fill) ---------
// MODE 0: C = A(M,K) * B(K,N)      (NN)
// MODE 1: C = A(M,K) * B(N,K)^T    (NT)
// MODE 2: C = A(K,M)^T * B(K,N)    (TN)
struct GemmP {
    const float* A; const float* B; float* C; const float* res;
    int M, N, K, lda, ldb, ldc;
    float alpha;
    long long aO1, aO2, bO1, bO2, cO1, cO2;
    int zdiv, cap;
    const int* Mvec;    // per-z dynamic M (row count)
    const int* aRows;   // per-z row gather indices into A
    const int* cRows;   // per-z row scatter indices into C (atomicAdd)
    const float* wRow;  // per-row scatter weight
};

__device__ __forceinline__ uint32_t f2t(float x) {
    uint32_t u; asm("cvt.rna.tf32.f32 %0, %1;" : "=r"(u) : "f"(x)); return u;
}

__device__ __forceinline__ void mma_tf32(float* c, const uint32_t* a, const uint32_t* b) {
    asm volatile("mma.sync.aligned.m16n8k8.row.col.f32.tf32.tf32.f32 "
        "{%0,%1,%2,%3}, {%4,%5,%6,%7}, {%8,%9}, {%0,%1,%2,%3};\n"
        : "+f"(c[0]), "+f"(c[1]), "+f"(c[2]), "+f"(c[3])
        : "r"(a[0]), "r"(a[1]), "r"(a[2]), "r"(a[3]), "r"(b[0]), "r"(b[1]));
}

template<int MODE>
__global__ __launch_bounds__(256) void gemm_k(GemmP p) {
    __shared__ uint32_t sAh[8][136], sAl[8][136], sBh[8][136], sBl[8][136];

    int z = blockIdx.z, z1 = z / p.zdiv, z2 = z - z1 * p.zdiv;
    const float* A  = p.A + z1 * p.aO1 + z2 * p.aO2;
    const float* Bp = p.B + z1 * p.bO1 + z2 * p.bO2;
    float*       C  = p.C + z1 * p.cO1 + z2 * p.cO2;
    int M = p.Mvec ? p.Mvec[z] : p.M;
    int m0 = blockIdx.y * 128, n0 = blockIdx.x * 128;
    if (m0 >= M) return;
    int tid = threadIdx.x, lane = tid & 31, warp = tid >> 5;
    int wm = (warp & 1) << 6, wn = (warp >> 1) << 5;   // warp tile 64x32
    int gid = lane >> 2, tg = lane & 3;

    // ---- per-thread load setup (zero-fill out of range; never clamp) ----
    bool aValid; const float* aPtr; int aK, aM;
    if (MODE != 2) {                    // A[row][k] rows of M
        int r = m0 + (tid >> 1);
        aValid = (r < M);
        long long ar = 0;
        if (aValid) ar = p.aRows ? (long long)p.aRows[(long long)z * p.cap + r]
                                 : (long long)r;
        aPtr = A + ar * (long long)p.lda + (tid & 1) * 4;
        aK = (tid & 1) * 4;  aM = tid >> 1;
    } else {                            // A[k][m]
        int m = m0 + (lane = (tid & 31)) * 4;
        aValid = (m < M);
        aPtr = A + (long long)(tid >> 5) * p.lda + (aValid ? m : 0);
        aK = tid >> 5;       aM = (tid & 31) * 4;
        lane = tid & 31;  // restore
    }
    bool bValid; const float* bPtr; int bK, bM;
    if (MODE == 1) {                    // B[n][k]
        int cl = n0 + (tid >> 1);
        bValid = (cl < p.N);
        bPtr = Bp + (bValid ? (long long)cl * p.ldb : 0) + (tid & 1) * 4;
        bK = (tid & 1) * 4;  bM = tid >> 1;
    } else {                            // B[k][n]
        int n = n0 + (tid & 31) * 4;
        bValid = (n < p.N);
        bPtr = Bp + (long long)(tid >> 5) * p.ldb + (bValid ? n : 0);
        bK = tid >> 5;       bM = (tid & 31) * 4;
    }

    float acc[4][4][4];
#pragma unroll
    for (int mi = 0; mi < 4; mi++)
#pragma unroll
        for (int ni = 0; ni < 4; ni++)
#pragma unroll
            for (int q = 0; q < 4; q++) acc[mi][ni][q] = 0.f;

    const float4 z4 = make_float4(0.f, 0.f, 0.f, 0.f);
    int nIter = p.K >> 3;

    float4 va = aValid ? *(const float4*)aPtr : z4;
    float4 vb = bValid ? *(const float4*)bPtr : z4;

    for (int it = 0; it < nIter; it++) {
        // store current chunk into smem (hi/lo split)
        {
            const float* a4 = (const float*)&va;
            const float* b4 = (const float*)&vb;
#pragma unroll
            for (int j = 0; j < 4; j++) {
                uint32_t hu = f2t(a4[j]);
                uint32_t lu = f2t(a4[j] - __uint_as_float(hu));
                if (MODE == 2) { sAh[aK][aM + j] = hu; sAl[aK][aM + j] = lu; }
                else           { sAh[aK + j][aM] = hu; sAl[aK + j][aM] = lu; }
                uint32_t hb = f2t(b4[j]);
                uint32_t lb = f2t(b4[j] - __uint_as_float(hb));
                if (MODE == 1) { sBh[bK + j][bM] = hb; sBl[bK + j][bM] = lb; }
                else           { sBh[bK][bM + j] = hb; sBl[bK][bM + j] = lb; }
            }
        }
        __syncthreads();

        // prefetch next chunk (global, overlaps with MMAs below)
        float4 na = z4, nb = z4;
        if (it + 1 < nIter) {
            long long ka = (MODE == 2) ? (long long)(it + 1) * 8 * p.lda
                                       : (long long)(it + 1) * 8;
            long long kb = (MODE == 1) ? (long long)(it + 1) * 8
                                       : (long long)(it + 1) * 8 * p.ldb;
            if (aValid) na = *(const float4*)(aPtr + ka);
            if (bValid) nb = *(const float4*)(bPtr + kb);
        }

        // fragments + 3 MMA passes over this k=8 chunk
        uint32_t ah[4][4], al[4][4], bh[4][2], bl[4][2];
#pragma unroll
        for (int mi = 0; mi < 4; mi++) {
            int mb = wm + mi * 16;
            ah[mi][0] = sAh[tg    ][mb + gid];
            ah[mi][1] = sAh[tg    ][mb + gid + 8];
            ah[mi][2] = sAh[tg + 4][mb + gid];
            ah[mi][3] = sAh[tg + 4][mb + gid + 8];
            al[mi][0] = sAl[tg    ][mb + gid];
            al[mi][1] = sAl[tg    ][mb + gid + 8];
            al[mi][2] = sAl[tg + 4][mb + gid];
            al[mi][3] = sAl[tg + 4][mb + gid + 8];
        }
#pragma unroll
        for (int ni = 0; ni < 4; ni++) {
            int nb2 = wn + ni * 8;
            bh[ni][0] = sBh[tg    ][nb2 + gid];
            bh[ni][1] = sBh[tg + 4][nb2 + gid];
            bl[ni][0] = sBl[tg    ][nb2 + gid];
            bl[ni][1] = sBl[tg + 4][nb2 + gid];
        }
#pragma unroll
        for (int mi = 0; mi < 4; mi++)
#pragma unroll
            for (int ni = 0; ni < 4; ni++)
                mma_tf32(acc[mi][ni], ah[mi], bh[ni]);
#pragma unroll
        for (int mi = 0; mi < 4; mi++)
#pragma unroll
            for (int ni = 0; ni < 4; ni++)
                mma_tf32(acc[mi][ni], al[mi], bh[ni]);
#pragma unroll
        for (int mi = 0; mi < 4; mi++)
#pragma unroll
            for (int ni = 0; ni < 4; ni++)
                mma_tf32(acc[mi][ni], ah[mi], bl[ni]);
        __syncthreads();
        va = na; vb = nb;
    }

    // epilogue: c0,c1 -> row gid, cols 2tg,2tg+1 ; c2,c3 -> row gid+8
#pragma unroll
    for (int mi = 0; mi < 4; mi++) {
#pragma unroll
        for (int half = 0; half < 2; half++) {
            int m = m0 + wm + mi * 16 + gid + half * 8;
            if (m >= M) continue;
            long long crow; float w = p.alpha;
            if (p.cRows) {
                crow = (long long)p.cRows[(long long)z * p.cap + m] * p.ldc;
                w *= p.wRow[(long long)z * p.cap + m];
            } else {
                crow = (long long)m * p.ldc;
            }
#pragma unroll
            for (int ni = 0; ni < 4; ni++) {
                int n = n0 + wn + ni * 8 + tg * 2;
                if (n >= p.N) continue;
                float v0 = acc[mi][ni][half * 2 + 0] * w;
                float v1 = acc[mi][ni][half * 2 + 1] * w;
                if (p.cRows) {
                    atomicAdd(&C[crow + n],     v0);
                    atomicAdd(&C[crow + n + 1], v1);
                } else {
                    if (p.res) { v0 += p.res[crow + n]; v1 += p.res[crow + n + 1]; }
                    C[crow + n]     = v0;
                    C[crow + n + 1] = v1;
                }
            }
        }
    }
}

// ---------------- small fused kernels -----------------------------------------
__global__ void rmsnorm_k(const float* __restrict__ x, const float* __restrict__ w,
                          float* __restrict__ o) {
    int r = blockIdx.x;
    const float* xr = x + (long long)r * DIM_;
    float s = 0.f;
    for (int d = threadIdx.x; d < DIM_; d += 256) { float v = xr[d]; s += v * v; }
    __shared__ float red[256];
    red[threadIdx.x] = s; __syncthreads();
    for (int off = 128; off; off >>= 1) {
        if (threadIdx.x < off) red[threadIdx.x] += red[threadIdx.x + off];
        __syncthreads();
    }
    float inv = rsqrtf(red[0] / (float)DIM_ + 1e-6f);
    float* orow = o + (long long)r * DIM_;
    for (int d = threadIdx.x; d < DIM_; d += 256) orow[d] = w[d] * xr[d] * inv;
}

__device__ __forceinline__ void rope_cs(int t, int j, float& c, float& s) {
    float freq = 1.0f / powf(10000.0f, (float)(2 * j) / (float)DRH_);
    float ang = (float)t * freq;
    sincosf(ang, &s, &c);
}

__global__ void rope_q_k(float* __restrict__ Q) {
    int idx = blockIdx.x;            // bt*NH + h
    int bt = idx / NH_;
    int t = bt % T_;
    int j = threadIdx.x;             // 0..31
    float* base = Q + (long long)idx * QKD_ + DH_;
    float re = base[j], im = base[32 + j];
    float c, s; rope_cs(t, j, c, s);
    base[j]      = re * c - im * s;
    base[32 + j] = re * s + im * c;
}

__global__ void rope_kr_k(const float* __restrict__ kr, float* __restrict__ Kb) {
    int bt = blockIdx.x;
    int t = bt % T_;
    int j = threadIdx.x;             // 0..31
    float re = kr[bt * DRH_ + j], im = kr[bt * DRH_ + 32 + j];
    float c, s; rope_cs(t, j, c, s);
    float o1 = (re * c - im * s) / (float)NH_;
    float o2 = (re * s + im * c) / (float)NH_;
    for (int h = 0; h < NH_; h++) {
        float* base = Kb + ((long long)bt * NH_ + h) * QKD_ + DH_;
        base[j] = o1; base[32 + j] = o2;
    }
}

__global__ void softmax_k(float* __restrict__ S) {
    long long r = blockIdx.x;        // (b,h,t) row
    int t = (int)(r & (T_ - 1));
    float* row = S + r * (long long)T_;
    int n = t + 1;
    __shared__ float red[256];
    int tid = threadIdx.x;
    float mx = -INFINITY;
    for (int l = tid; l < n; l += 256) mx = fmaxf(mx, row[l]);
    red[tid] = mx; __syncthreads();
    for (int off = 128; off; off >>= 1) {
        if (tid < off) red[tid] = fmaxf(red[tid], red[tid + off]);
        __syncthreads();
    }
    mx = red[0]; __syncthreads();
    float sum = 0.f;
    for (int l = tid; l < n; l += 256) { float e = expf(row[l] - mx); row[l] = e; sum += e; }
    red[tid] = sum; __syncthreads();
    for (int off = 128; off; off >>= 1) {
        if (tid < off) red[tid] += red[tid + off];
        __syncthreads();
    }
    float inv = 1.f / red[0];
    for (int l = tid; l < T_; l += 256) row[l] = (l < n) ? row[l] * inv : 0.f;
}

__global__ void pack_wo_k(const float* __restrict__ wo, float* __restrict__ out) {
    long long i = (long long)blockIdx.x * 256 + threadIdx.x;  // d*2048 + h*128 + k
    if (i >= (long long)DIM_ * 2048) return;
    int d = (int)(i >> 11);
    int r = (int)(i & 2047);
    int h = r >> 7, k = r & 127;
    out[i] = wo[(long long)d * 2048 + k * NH_ + h];
}

__global__ void gate_k(const float* __restrict__ xn, const float* __restrict__ gw,
                       const float* __restrict__ gb, float* affOut,
                       int* __restrict__ cnt, int* __restrict__ tok,
                       float* __restrict__ wt) {
    int bt = blockIdx.x;
    __shared__ float xrow[DIM_];
    __shared__ float aff[NE_];
    int tid = threadIdx.x;
    for (int d = tid; d < DIM_; d += 256) xrow[d] = xn[(long long)bt * DIM_ + d];
    __syncthreads();
    int w = tid >> 5, lane = tid & 31;
    for (int e = w; e < NE_; e += 8) {
        float s = 0.f;
        const float* gr = gw + (long long)e * DIM_;
        for (int d = lane; d < DIM_; d += 32) s += xrow[d] * gr[d];
        for (int o = 16; o; o >>= 1) s += __shfl_xor_sync(0xffffffffu, s, o);
        if (lane == 0) aff[e] = 1.f / (1.f + expf(-s)) + gb[e];
    }
    __syncthreads();
    if (tid == 0) {
        if (affOut) for (int e = 0; e < NE_; e++) affOut[(long long)bt * NE_ + e] = aff[e];
        bool used[NE_] = {};
        float wv[TOPK_]; int wi[TOPK_]; float sum = 0.f;
        for (int k = 0; k < TOPK_; k++) {
            float best = -1e30f; int bi = 0;
            for (int e = 0; e < NE_; e++)
                if (!used[e] && aff[e] > best) { best = aff[e]; bi = e; }
            used[bi] = true; wv[k] = best; wi[k] = bi; sum += best;
        }
        for (int k = 0; k < TOPK_; k++) {
            int e = wi[k];
            int pos = atomicAdd(&cnt[e], 1);
            tok[e * CAP_ + pos] = bt;
            wt [e * CAP_ + pos] = wv[k] / sum;
        }
    }
}

__global__ void silumul_k(float* __restrict__ a, const float* __restrict__ b, long long n) {
    long long i = (long long)blockIdx.x * 256 + threadIdx.x;
    if (i < n) { float z = a[i] * b[i]; a[i] = z / (1.f + expf(-z)); }
}

__global__ void silumul_routed_k(float* __restrict__ a, const float* __restrict__ b,
                                 const int* __restrict__ cnt) {
    long long i = (long long)blockIdx.x * 256 + threadIdx.x;   // NE*CAP*MOE
    int e = (int)(i >> 21);                // CAP_*MOE_ = 2^21
    int ri = (int)((i >> 10) & (CAP_ - 1));
    if (ri >= cnt[e]) return;
    float z = a[i] * b[i];
    a[i] = z / (1.f + expf(-z));
}

// ---------------- host-side launch helpers ------------------------------------
template<int MODE>
static void gemm(const float* A, const float* B, float* C, int M, int N, int K,
                 int lda, int ldb, int ldc, float alpha, const float* res,
                 int nz, int zdiv,
                 long long a1, long long a2, long long b1, long long b2,
                 long long c1, long long c2,
                 const int* Mvec = nullptr, const int* aRows = nullptr,
                 const int* cRows = nullptr, const float* wRow = nullptr,
                 int cap = 0) {
    GemmP p;
    p.A = A; p.B = B; p.C = C; p.res = res;
    p.M = M; p.N = N; p.K = K; p.lda = lda; p.ldb = ldb; p.ldc = ldc;
    p.alpha = alpha;
    p.aO1 = a1; p.aO2 = a2; p.bO1 = b1; p.bO2 = b2; p.cO1 = c1; p.cO2 = c2;
    p.zdiv = zdiv; p.cap = cap;
    p.Mvec = Mvec; p.aRows = aRows; p.cRows = cRows; p.wRow = wRow;
    dim3 g((N + 127) / 128, (M + 127) / 128, nz);
    gemm_k<MODE><<<g, 256>>>(p);
}

extern "C" void kernel_launch(void* const* d_in, const int* in_sizes, int n_in,
                              void* d_out, int out_size) {
    const float* x      = (const float*)d_in[0];
    const float* attn_w = (const float*)d_in[3];
    const float* ffn_w  = (const float*)d_in[4];
    const float* gate_w = (const float*)d_in[5];
    const float* gate_b = (const float*)d_in[6];
    const float* w1s    = (const float*)d_in[7];
    const float* w2s    = (const float*)d_in[8];
    const float* w3s    = (const float*)d_in[9];
    const float* w1r    = (const float*)d_in[10];
    const float* w2r    = (const float*)d_in[11];
    const float* w3r    = (const float*)d_in[12];
    const float* wdkv   = (const float*)d_in[13];
    const float* wuk    = (const float*)d_in[14];
    const float* wuv    = (const float*)d_in[15];
    const float* wdq    = (const float*)d_in[16];
    const float* wuq    = (const float*)d_in[17];
    const float* wqr    = (const float*)d_in[18];
    const float* wkr    = (const float*)d_in[19];
    const float* wo     = (const float*)d_in[20];
    float* out = (float*)d_out;

    float *h, *ckv, *cq, *Q, *K, *V, *kr, *S, *O, *Wo, *x1, *xn, *a1, *a3, *h1, *h2, *wt;
    int *cnt, *tok;
    cudaGetSymbolAddress((void**)&h,   g_h);
    cudaGetSymbolAddress((void**)&ckv, g_ckv);
    cudaGetSymbolAddress((void**)&cq,  g_cq);
    cudaGetSymbolAddress((void**)&Q,   g_Q);
    cudaGetSymbolAddress((void**)&K,   g_K);
    cudaGetSymbolAddress((void**)&V,   g_V);
    cudaGetSymbolAddress((void**)&kr,  g_kr);
    cudaGetSymbolAddress((void**)&S,   g_S);
    cudaGetSymbolAddress((void**)&O,   g_O);
    cudaGetSymbolAddress((void**)&Wo,  g_Wo);
    cudaGetSymbolAddress((void**)&x1,  g_x1);
    cudaGetSymbolAddress((void**)&xn,  g_xn);
    cudaGetSymbolAddress((void**)&a1,  g_a1);
    cudaGetSymbolAddress((void**)&a3,  g_a3);
    cudaGetSymbolAddress((void**)&h1,  g_h1);
    cudaGetSymbolAddress((void**)&h2,  g_h2);
    cudaGetSymbolAddress((void**)&cnt, g_cnt);
    cudaGetSymbolAddress((void**)&tok, g_tok);
    cudaGetSymbolAddress((void**)&wt,  g_wt);

    // ---- attention ----
    rmsnorm_k<<<BT_, 256>>>(x, attn_w, h);
    // c_kv, c_q : (BT,DIM) x (DC,DIM)^T
    gemm<1>(h, wdkv, ckv, BT_, DC_, DIM_, DIM_, DIM_, DC_, 1.f, nullptr, 1, 1, 0,0,0,0,0,0);
    gemm<1>(h, wdq,  cq,  BT_, DC_, DIM_, DIM_, DIM_, DC_, 1.f, nullptr, 1, 1, 0,0,0,0,0,0);
    // per-head up-projections (batched over h; weight row stride NH*DC, sub-offset h*DC)
    gemm<1>(ckv, wuk, K,       BT_, DH_,  DC_, DC_, NH_*DC_, NH_*QKD_, 1.f, nullptr,
            NH_, NH_, 0,0, 0, DC_, 0, QKD_);
    gemm<1>(ckv, wuv, V,       BT_, DH_,  DC_, DC_, NH_*DC_, NH_*DH_,  1.f, nullptr,
            NH_, NH_, 0,0, 0, DC_, 0, DH_);
    gemm<1>(cq,  wuq, Q,       BT_, DH_,  DC_, DC_, NH_*DC_, NH_*QKD_, 1.f, nullptr,
            NH_, NH_, 0,0, 0, DC_, 0, QKD_);
    gemm<1>(cq,  wqr, Q + DH_, BT_, DRH_, DC_, DC_, NH_*DC_, NH_*QKD_, 1.f, nullptr,
            NH_, NH_, 0,0, 0, DC_, 0, QKD_);
    // k_r = h @ w_kr^T
    gemm<1>(h, wkr, kr, BT_, DRH_, DIM_, DIM_, DIM_, DRH_, 1.f, nullptr, 1, 1, 0,0,0,0,0,0);
    rope_q_k<<<BT_ * NH_, 32>>>(Q);
    rope_kr_k<<<BT_, 32>>>(kr, K);
    // logits (batched over b,h), scaled
    float scale = 1.0f / sqrtf((float)QKD_);
    gemm<1>(Q, K, S, T_, T_, QKD_, NH_*QKD_, NH_*QKD_, T_, scale, nullptr,
            B_*NH_, NH_,
            (long long)T_*NH_*QKD_, QKD_,
            (long long)T_*NH_*QKD_, QKD_,
            (long long)NH_*T_*T_, (long long)T_*T_);
    softmax_k<<<B_ * NH_ * T_, 256>>>(S);
    // out[l,k] = sum_t S[t,l] V[t,k]  (TN)
    gemm<2>(S, V, O, T_, DH_, T_, T_, NH_*DH_, NH_*DH_, 1.f, nullptr,
            B_*NH_, NH_,
            (long long)NH_*T_*T_, (long long)T_*T_,
            (long long)T_*NH_*DH_, DH_,
            (long long)T_*NH_*DH_, DH_);
    // attn projection + residual
    pack_wo_k<<<(DIM_*2048 + 255)/256, 256>>>(wo, Wo);
    gemm<1>(O, Wo, x1, BT_, DIM_, NH_*DH_, NH_*DH_, NH_*DH_, DIM_, 1.f, x,
            1, 1, 0,0,0,0,0,0);

    // ---- MoE ----
    rmsnorm_k<<<BT_, 256>>>(x1, ffn_w, xn);
    cudaMemsetAsync(cnt, 0, NE_ * sizeof(int));
    float* affOut = (out_size >= BT_*DIM_ + BT_*NE_) ? out + (long long)BT_*DIM_ : nullptr;
    gate_k<<<BT_, 256>>>(xn, gate_w, gate_b, affOut, cnt, tok, wt);
    // shared expert
    gemm<0>(xn, w1s, a1, BT_, MOESH_, DIM_, DIM_, MOESH_, MOESH_, 1.f, nullptr, 1,1,0,0,0,0,0,0);
    gemm<0>(xn, w3s, a3, BT_, MOESH_, DIM_, DIM_, MOESH_, MOESH_, 1.f, nullptr, 1,1,0,0,0,0,0,0);
    silumul_k<<<(BT_*MOESH_ + 255)/256, 256>>>(a1, a3, (long long)BT_*MOESH_);
    gemm<0>(a1, w2s, out, BT_, DIM_, MOESH_, MOESH_, DIM_, DIM_, 1.f, x1, 1,1,0,0,0,0,0,0);
    // routed experts (top-4 only; gathered GEMMs with dynamic M, fused weighted scatter)
    gemm<0>(xn, w1r, h1, CAP_, MOE_, DIM_, DIM_, MOE_, MOE_, 1.f, nullptr,
            NE_, NE_, 0,0, 0, (long long)DIM_*MOE_, 0, (long long)CAP_*MOE_,
            cnt, tok, nullptr, nullptr, CAP_);
    gemm<0>(xn, w3r, h2, CAP_, MOE_, DIM_, DIM_, MOE_, MOE_, 1.f, nullptr,
            NE_, NE_, 0,0, 0, (long long)DIM_*MOE_, 0, (long long)CAP_*MOE_,
            cnt, tok, nullptr, nullptr, CAP_);
    silumul_routed_k<<<((long long)NE_*CAP_*MOE_ + 255)/256, 256>>>(h1, h2, cnt);
    gemm<0>(h1, w2r, out, CAP_, DIM_, MOE_, MOE_, DIM_, DIM_, 1.f, nullptr,
            NE_, NE_, 0, (long long)CAP_*MOE_, 0, (long long)MOE_*DIM_, 0, 0,
            cnt, nullptr, tok, wt, CAP_);
}

// round 5
// speedup vs baseline: 1.2249x; 1.0295x over previous
#include <cuda_runtime.h>
#include <cuda_bf16.h>
#include <math.h>
#include <stdint.h>

#define B_    2
#define T_    1024
#define BT_   2048
#define DIM_  2048
#define NH_   16
#define DH_   128
#define DRH_  64
#define DC_   512
#define NE_   16
#define TOPK_ 4
#define MOE_  1024
#define MOESH_ 2048
#define CAP_  2048
#define QKD_  192   // DH + DRH

// ---------------- scratch (static device globals; no runtime alloc) ----------
__device__ float g_h  [BT_*DIM_];
__device__ float g_ckv[BT_*DC_];
__device__ float g_cq [BT_*DC_];
__device__ float g_Q  [BT_*NH_*QKD_];
__device__ float g_K  [BT_*NH_*QKD_];
__device__ float g_V  [BT_*NH_*DH_];
__device__ float g_kr [BT_*DRH_];
__device__ float g_S  [(size_t)B_*NH_*T_*T_];
__device__ float g_O  [BT_*NH_*DH_];
__device__ float g_Wo [DIM_*NH_*DH_];
__device__ float g_x1 [BT_*DIM_];
__device__ float g_xn [BT_*DIM_];
__device__ float g_a1 [BT_*MOESH_];
__device__ float g_a3 [BT_*MOESH_];
__device__ float g_h1 [(size_t)NE_*CAP_*MOE_];
__device__ float g_h2 [(size_t)NE_*CAP_*MOE_];
__device__ int   g_cnt[NE_];
__device__ int   g_tok[NE_*CAP_];
__device__ float g_wt [NE_*CAP_];

// ---------------- 3xTF32 tensor-core GEMM (single-buffer BK=16, zero-fill) ----
// MODE 0: C = A(M,K) * B(K,N)      (NN)
// MODE 1: C = A(M,K) * B(N,K)^T    (NT)
// MODE 2: C = A(K,M)^T * B(K,N)    (TN)
struct GemmP {
    const float* A; const float* B; float* C; const float* res;
    int M, N, K, lda, ldb, ldc;
    float alpha;
    long long aO1, aO2, bO1, bO2, cO1, cO2;
    int zdiv, cap;
    const int* Mvec;    // per-z dynamic M (row count)
    const int* aRows;   // per-z row gather indices into A
    const int* cRows;   // per-z row scatter indices into C (atomicAdd)
    const float* wRow;  // per-row scatter weight
    int causal;         // MODE1 logits: skip blocks entirely above diagonal
    int causalAV;       // MODE2 AV: K loop starts at m0 (S lower-triangular)
};

__device__ __forceinline__ uint32_t f2t(float x) {
    uint32_t u; asm("cvt.rna.tf32.f32 %0, %1;" : "=r"(u) : "f"(x)); return u;
}

__device__ __forceinline__ void mma_tf32(float* c, const uint32_t* a, const uint32_t* b) {
    asm volatile("mma.sync.aligned.m16n8k8.row.col.f32.tf32.tf32.f32 "
        "{%0,%1,%2,%3}, {%4,%5,%6,%7}, {%8,%9}, {%0,%1,%2,%3};\n"
        : "+f"(c[0]), "+f"(c[1]), "+f"(c[2]), "+f"(c[3])
        : "r"(a[0]), "r"(a[1]), "r"(a[2]), "r"(a[3]), "r"(b[0]), "r"(b[1]));
}

template<int MODE>
__global__ __launch_bounds__(256) void gemm_k(GemmP p) {
    __shared__ uint32_t sAh[16][136], sAl[16][136], sBh[16][136], sBl[16][136];

    int z = blockIdx.z, z1 = z / p.zdiv, z2 = z - z1 * p.zdiv;
    const float* A  = p.A + z1 * p.aO1 + z2 * p.aO2;
    const float* Bp = p.B + z1 * p.bO1 + z2 * p.bO2;
    float*       C  = p.C + z1 * p.cO1 + z2 * p.cO2;
    int M = p.Mvec ? p.Mvec[z] : p.M;
    int m0 = blockIdx.y * 128, n0 = blockIdx.x * 128;
    if (m0 >= M) return;
    if (MODE == 1 && p.causal && n0 >= m0 + 128) return;  // fully masked block
    int tid = threadIdx.x, lane = tid & 31, warp = tid >> 5;
    int wm = (warp & 1) << 6, wn = (warp >> 1) << 5;   // warp tile 64x32
    int gid = lane >> 2, tg = lane & 3;

    // ---- per-thread load setup (zero-fill out of range; never clamp) ----
    bool aValid[2]; const float* aPtr[2]; int aK[2], aM[2];
    bool bValid[2]; const float* bPtr[2]; int bK[2], bM[2];
#pragma unroll
    for (int s = 0; s < 2; s++) {
        int idx = tid + s * 256;
        if (MODE != 2) {                // A[row][k], rows of M; 128 rows x 16 k
            int r = m0 + (idx >> 2);
            aValid[s] = (r < M);
            long long ar = 0;
            if (aValid[s]) ar = p.aRows ? (long long)p.aRows[(long long)z * p.cap + r]
                                        : (long long)r;
            aPtr[s] = A + ar * (long long)p.lda + (idx & 3) * 4;
            aK[s] = (idx & 3) * 4;  aM[s] = idx >> 2;
        } else {                        // A[k][m]; 16 k x 128 m
            int m = m0 + (idx & 31) * 4;
            aValid[s] = (m < M);
            aPtr[s] = A + (long long)(idx >> 5) * p.lda + (aValid[s] ? m : 0);
            aK[s] = idx >> 5;       aM[s] = (idx & 31) * 4;
        }
        if (MODE == 1) {                // B[n][k]
            int cl = n0 + (idx >> 2);
            bValid[s] = (cl < p.N);
            bPtr[s] = Bp + (bValid[s] ? (long long)cl * p.ldb : 0) + (idx & 3) * 4;
            bK[s] = (idx & 3) * 4;  bM[s] = idx >> 2;
        } else {                        // B[k][n]
            int n = n0 + (idx & 31) * 4;
            bValid[s] = (n < p.N);
            bPtr[s] = Bp + (long long)(idx >> 5) * p.ldb + (bValid[s] ? n : 0);
            bK[s] = idx >> 5;       bM[s] = (idx & 31) * 4;
        }
    }

    float acc[4][4][4];
#pragma unroll
    for (int mi = 0; mi < 4; mi++)
#pragma unroll
        for (int ni = 0; ni < 4; ni++)
#pragma unroll
            for (int q = 0; q < 4; q++) acc[mi][ni][q] = 0.f;

    const float4 z4 = make_float4(0.f, 0.f, 0.f, 0.f);
    int kStart = (MODE == 2 && p.causalAV) ? (m0 & ~15) : 0;
    int nIter = (p.K - kStart) >> 4;

    float4 va[2], vb[2];
#pragma unroll
    for (int s = 0; s < 2; s++) {
        long long ka = (MODE == 2) ? (long long)kStart * p.lda : (long long)kStart;
        long long kb = (MODE == 1) ? (long long)kStart : (long long)kStart * p.ldb;
        va[s] = aValid[s] ? *(const float4*)(aPtr[s] + ka) : z4;
        vb[s] = bValid[s] ? *(const float4*)(bPtr[s] + kb) : z4;
    }

    for (int it = 0; it < nIter; it++) {
        // store current 16-K chunk into smem (hi/lo split)
#pragma unroll
        for (int s = 0; s < 2; s++) {
            const float* a4 = (const float*)&va[s];
            const float* b4 = (const float*)&vb[s];
#pragma unroll
            for (int j = 0; j < 4; j++) {
                uint32_t hu = f2t(a4[j]);
                uint32_t lu = f2t(a4[j] - __uint_as_float(hu));
                if (MODE == 2) { sAh[aK[s]][aM[s] + j] = hu; sAl[aK[s]][aM[s] + j] = lu; }
                else           { sAh[aK[s] + j][aM[s]] = hu; sAl[aK[s] + j][aM[s]] = lu; }
                uint32_t hb = f2t(b4[j]);
                uint32_t lb = f2t(b4[j] - __uint_as_float(hb));
                if (MODE == 1) { sBh[bK[s] + j][bM[s]] = hb; sBl[bK[s] + j][bM[s]] = lb; }
                else           { sBh[bK[s]][bM[s] + j] = hb; sBl[bK[s]][bM[s] + j] = lb; }
            }
        }
        __syncthreads();

        // prefetch next chunk (overlaps with MMAs below)
        float4 na[2] = {z4, z4}, nb[2] = {z4, z4};
        if (it + 1 < nIter) {
            int kNext = kStart + (it + 1) * 16;
            long long ka = (MODE == 2) ? (long long)kNext * p.lda : (long long)kNext;
            long long kb = (MODE == 1) ? (long long)kNext : (long long)kNext * p.ldb;
#pragma unroll
            for (int s = 0; s < 2; s++) {
                if (aValid[s]) na[s] = *(const float4*)(aPtr[s] + ka);
                if (bValid[s]) nb[s] = *(const float4*)(bPtr[s] + kb);
            }
        }

        // two k=8 sub-chunks, 3 MMA passes each
#pragma unroll
        for (int kk = 0; kk < 16; kk += 8) {
            uint32_t ah[4][4], al[4][4], bh[4][2], bl[4][2];
#pragma unroll
            for (int mi = 0; mi < 4; mi++) {
                int mb = wm + mi * 16;
                ah[mi][0] = sAh[kk + tg    ][mb + gid];
                ah[mi][1] = sAh[kk + tg    ][mb + gid + 8];
                ah[mi][2] = sAh[kk + tg + 4][mb + gid];
                ah[mi][3] = sAh[kk + tg + 4][mb + gid + 8];
                al[mi][0] = sAl[kk + tg    ][mb + gid];
                al[mi][1] = sAl[kk + tg    ][mb + gid + 8];
                al[mi][2] = sAl[kk + tg + 4][mb + gid];
                al[mi][3] = sAl[kk + tg + 4][mb + gid + 8];
            }
#pragma unroll
            for (int ni = 0; ni < 4; ni++) {
                int nb2 = wn + ni * 8;
                bh[ni][0] = sBh[kk + tg    ][nb2 + gid];
                bh[ni][1] = sBh[kk + tg + 4][nb2 + gid];
                bl[ni][0] = sBl[kk + tg    ][nb2 + gid];
                bl[ni][1] = sBl[kk + tg + 4][nb2 + gid];
            }
#pragma unroll
            for (int mi = 0; mi < 4; mi++)
#pragma unroll
                for (int ni = 0; ni < 4; ni++)
                    mma_tf32(acc[mi][ni], ah[mi], bh[ni]);
#pragma unroll
            for (int mi = 0; mi < 4; mi++)
#pragma unroll
                for (int ni = 0; ni < 4; ni++)
                    mma_tf32(acc[mi][ni], al[mi], bh[ni]);
#pragma unroll
            for (int mi = 0; mi < 4; mi++)
#pragma unroll
                for (int ni = 0; ni < 4; ni++)
                    mma_tf32(acc[mi][ni], ah[mi], bl[ni]);
        }
        __syncthreads();
#pragma unroll
        for (int s = 0; s < 2; s++) { va[s] = na[s]; vb[s] = nb[s]; }
    }

    // epilogue: c0,c1 -> row gid, cols 2tg,2tg+1 ; c2,c3 -> row gid+8
#pragma unroll
    for (int mi = 0; mi < 4; mi++) {
#pragma unroll
        for (int half = 0; half < 2; half++) {
            int m = m0 + wm + mi * 16 + gid + half * 8;
            if (m >= M) continue;
            long long crow; float w = p.alpha;
            if (p.cRows) {
                crow = (long long)p.cRows[(long long)z * p.cap + m] * p.ldc;
                w *= p.wRow[(long long)z * p.cap + m];
            } else {
                crow = (long long)m * p.ldc;
            }
#pragma unroll
            for (int ni = 0; ni < 4; ni++) {
                int n = n0 + wn + ni * 8 + tg * 2;
                if (n >= p.N) continue;
                float v0 = acc[mi][ni][half * 2 + 0] * w;
                float v1 = acc[mi][ni][half * 2 + 1] * w;
                if (p.cRows) {
                    atomicAdd(&C[crow + n],     v0);
                    atomicAdd(&C[crow + n + 1], v1);
                } else {
                    if (p.res) { v0 += p.res[crow + n]; v1 += p.res[crow + n + 1]; }
                    C[crow + n]     = v0;
                    C[crow + n + 1] = v1;
                }
            }
        }
    }
}

// ---------------- small fused kernels -----------------------------------------
__global__ void rmsnorm_k(const float* __restrict__ x, const float* __restrict__ w,
                          float* __restrict__ o) {
    int r = blockIdx.x;
    const float* xr = x + (long long)r * DIM_;
    float s = 0.f;
    for (int d = threadIdx.x; d < DIM_; d += 256) { float v = xr[d]; s += v * v; }
    __shared__ float red[256];
    red[threadIdx.x] = s; __syncthreads();
    for (int off = 128; off; off >>= 1) {
        if (threadIdx.x < off) red[threadIdx.x] += red[threadIdx.x + off];
        __syncthreads();
    }
    float inv = rsqrtf(red[0] / (float)DIM_ + 1e-6f);
    float* orow = o + (long long)r * DIM_;
    for (int d = threadIdx.x; d < DIM_; d += 256) orow[d] = w[d] * xr[d] * inv;
}

__device__ __forceinline__ void rope_cs(int t, int j, float& c, float& s) {
    float freq = 1.0f / powf(10000.0f, (float)(2 * j) / (float)DRH_);
    float ang = (float)t * freq;
    sincosf(ang, &s, &c);
}

__global__ void rope_q_k(float* __restrict__ Q) {
    int idx = blockIdx.x;            // bt*NH + h
    int bt = idx / NH_;
    int t = bt % T_;
    int j = threadIdx.x;             // 0..31
    float* base = Q + (long long)idx * QKD_ + DH_;
    float re = base[j], im = base[32 + j];
    float c, s; rope_cs(t, j, c, s);
    base[j]      = re * c - im * s;
    base[32 + j] = re * s + im * c;
}

__global__ void rope_kr_k(const float* __restrict__ kr, float* __restrict__ Kb) {
    int bt = blockIdx.x;
    int t = bt % T_;
    int j = threadIdx.x;             // 0..31
    float re = kr[bt * DRH_ + j], im = kr[bt * DRH_ + 32 + j];
    float c, s; rope_cs(t, j, c, s);
    float o1 = (re * c - im * s) / (float)NH_;
    float o2 = (re * s + im * c) / (float)NH_;
    for (int h = 0; h < NH_; h++) {
        float* base = Kb + ((long long)bt * NH_ + h) * QKD_ + DH_;
        base[j] = o1; base[32 + j] = o2;
    }
}

__global__ void softmax_k(float* __restrict__ S) {
    long long r = blockIdx.x;        // (b,h,t) row
    int t = (int)(r & (T_ - 1));
    float* row = S + r * (long long)T_;
    int n = t + 1;
    __shared__ float red[256];
    int tid = threadIdx.x;
    float mx = -INFINITY;
    for (int l = tid; l < n; l += 256) mx = fmaxf(mx, row[l]);
    red[tid] = mx; __syncthreads();
    for (int off = 128; off; off >>= 1) {
        if (tid < off) red[tid] = fmaxf(red[tid], red[tid + off]);
        __syncthreads();
    }
    mx = red[0]; __syncthreads();
    float sum = 0.f;
    for (int l = tid; l < n; l += 256) { float e = expf(row[l] - mx); row[l] = e; sum += e; }
    red[tid] = sum; __syncthreads();
    for (int off = 128; off; off >>= 1) {
        if (tid < off) red[tid] += red[tid + off];
        __syncthreads();
    }
    float inv = 1.f / red[0];
    for (int l = tid; l < T_; l += 256) row[l] = (l < n) ? row[l] * inv : 0.f;
}

__global__ void pack_wo_k(const float* __restrict__ wo, float* __restrict__ out) {
    long long i = (long long)blockIdx.x * 256 + threadIdx.x;  // d*2048 + h*128 + k
    if (i >= (long long)DIM_ * 2048) return;
    int d = (int)(i >> 11);
    int r = (int)(i & 2047);
    int h = r >> 7, k = r & 127;
    out[i] = wo[(long long)d * 2048 + k * NH_ + h];
}

__global__ void gate_k(const float* __restrict__ xn, const float* __restrict__ gw,
                       const float* __restrict__ gb, float* affOut,
                       int* __restrict__ cnt, int* __restrict__ tok,
                       float* __restrict__ wt) {
    int bt = blockIdx.x;
    __shared__ float xrow[DIM_];
    __shared__ float aff[NE_];
    int tid = threadIdx.x;
    for (int d = tid; d < DIM_; d += 256) xrow[d] = xn[(long long)bt * DIM_ + d];
    __syncthreads();
    int w = tid >> 5, lane = tid & 31;
    for (int e = w; e < NE_; e += 8) {
        float s = 0.f;
        const float* gr = gw + (long long)e * DIM_;
        for (int d = lane; d < DIM_; d += 32) s += xrow[d] * gr[d];
        for (int o = 16; o; o >>= 1) s += __shfl_xor_sync(0xffffffffu, s, o);
        if (lane == 0) aff[e] = 1.f / (1.f + expf(-s)) + gb[e];
    }
    __syncthreads();
    if (tid == 0) {
        if (affOut) for (int e = 0; e < NE_; e++) affOut[(long long)bt * NE_ + e] = aff[e];
        bool used[NE_] = {};
        float wv[TOPK_]; int wi[TOPK_]; float sum = 0.f;
        for (int k = 0; k < TOPK_; k++) {
            float best = -1e30f; int bi = 0;
            for (int e = 0; e < NE_; e++)
                if (!used[e] && aff[e] > best) { best = aff[e]; bi = e; }
            used[bi] = true; wv[k] = best; wi[k] = bi; sum += best;
        }
        for (int k = 0; k < TOPK_; k++) {
            int e = wi[k];
            int pos = atomicAdd(&cnt[e], 1);
            tok[e * CAP_ + pos] = bt;
            wt [e * CAP_ + pos] = wv[k] / sum;
        }
    }
}

__global__ void silumul_k(float4* __restrict__ a, const float4* __restrict__ b, long long n4) {
    long long i = (long long)blockIdx.x * 256 + threadIdx.x;
    if (i >= n4) return;
    float4 x = a[i], y = b[i];
    x.x *= y.x; x.y *= y.y; x.z *= y.z; x.w *= y.w;
    x.x = x.x / (1.f + expf(-x.x));
    x.y = x.y / (1.f + expf(-x.y));
    x.z = x.z / (1.f + expf(-x.z));
    x.w = x.w / (1.f + expf(-x.w));
    a[i] = x;
}

__global__ void silumul_routed_k(float4* __restrict__ a, const float4* __restrict__ b,
                                 const int* __restrict__ cnt) {
    long long i = (long long)blockIdx.x * 256 + threadIdx.x;   // NE*CAP*MOE/4
    long long el = i << 2;
    int e = (int)(el >> 21);                // CAP_*MOE_ = 2^21
    int ri = (int)((el >> 10) & (CAP_ - 1));
    if (ri >= cnt[e]) return;
    float4 x = a[i], y = b[i];
    x.x *= y.x; x.y *= y.y; x.z *= y.z; x.w *= y.w;
    x.x = x.x / (1.f + expf(-x.x));
    x.y = x.y / (1.f + expf(-x.y));
    x.z = x.z / (1.f + expf(-x.z));
    x.w = x.w / (1.f + expf(-x.w));
    a[i] = x;
}

// ---------------- host-side launch helpers ------------------------------------
template<int MODE>
static void gemm(const float* A, const float* B, float* C, int M, int N, int K,
                 int lda, int ldb, int ldc, float alpha, const float* res,
                 int nz, int zdiv,
                 long long a1, long long a2, long long b1, long long b2,
                 long long c1, long long c2,
                 const int* Mvec = nullptr, const int* aRows = nullptr,
                 const int* cRows = nullptr, const float* wRow = nullptr,
                 int cap = 0, int causal = 0, int causalAV = 0) {
    GemmP p;
    p.A = A; p.B = B; p.C = C; p.res = res;
    p.M = M; p.N = N; p.K = K; p.lda = lda; p.ldb = ldb; p.ldc = ldc;
    p.alpha = alpha;
    p.aO1 = a1; p.aO2 = a2; p.bO1 = b1; p.bO2 = b2; p.cO1 = c1; p.cO2 = c2;
    p.zdiv = zdiv; p.cap = cap;
    p.Mvec = Mvec; p.aRows = aRows; p.cRows = cRows; p.wRow = wRow;
    p.causal = causal; p.causalAV = causalAV;
    dim3 g((N + 127) / 128, (M + 127) / 128, nz);
    gemm_k<MODE><<<g, 256>>>(p);
}

extern "C" void kernel_launch(void* const* d_in, const int* in_sizes, int n_in,
                              void* d_out, int out_size) {
    const float* x      = (const float*)d_in[0];
    const float* attn_w = (const float*)d_in[3];
    const float* ffn_w  = (const float*)d_in[4];
    const float* gate_w = (const float*)d_in[5];
    const float* gate_b = (const float*)d_in[6];
    const float* w1s    = (const float*)d_in[7];
    const float* w2s    = (const float*)d_in[8];
    const float* w3s    = (const float*)d_in[9];
    const float* w1r    = (const float*)d_in[10];
    const float* w2r    = (const float*)d_in[11];
    const float* w3r    = (const float*)d_in[12];
    const float* wdkv   = (const float*)d_in[13];
    const float* wuk    = (const float*)d_in[14];
    const float* wuv    = (const float*)d_in[15];
    const float* wdq    = (const float*)d_in[16];
    const float* wuq    = (const float*)d_in[17];
    const float* wqr    = (const float*)d_in[18];
    const float* wkr    = (const float*)d_in[19];
    const float* wo     = (const float*)d_in[20];
    float* out = (float*)d_out;

    float *h, *ckv, *cq, *Q, *K, *V, *kr, *S, *O, *Wo, *x1, *xn, *a1, *a3, *h1, *h2, *wt;
    int *cnt, *tok;
    cudaGetSymbolAddress((void**)&h,   g_h);
    cudaGetSymbolAddress((void**)&ckv, g_ckv);
    cudaGetSymbolAddress((void**)&cq,  g_cq);
    cudaGetSymbolAddress((void**)&Q,   g_Q);
    cudaGetSymbolAddress((void**)&K,   g_K);
    cudaGetSymbolAddress((void**)&V,   g_V);
    cudaGetSymbolAddress((void**)&kr,  g_kr);
    cudaGetSymbolAddress((void**)&S,   g_S);
    cudaGetSymbolAddress((void**)&O,   g_O);
    cudaGetSymbolAddress((void**)&Wo,  g_Wo);
    cudaGetSymbolAddress((void**)&x1,  g_x1);
    cudaGetSymbolAddress((void**)&xn,  g_xn);
    cudaGetSymbolAddress((void**)&a1,  g_a1);
    cudaGetSymbolAddress((void**)&a3,  g_a3);
    cudaGetSymbolAddress((void**)&h1,  g_h1);
    cudaGetSymbolAddress((void**)&h2,  g_h2);
    cudaGetSymbolAddress((void**)&cnt, g_cnt);
    cudaGetSymbolAddress((void**)&tok, g_tok);
    cudaGetSymbolAddress((void**)&wt,  g_wt);

    // ---- attention ----
    rmsnorm_k<<<BT_, 256>>>(x, attn_w, h);
    gemm<1>(h, wdkv, ckv, BT_, DC_, DIM_, DIM_, DIM_, DC_, 1.f, nullptr, 1, 1, 0,0,0,0,0,0);
    gemm<1>(h, wdq,  cq,  BT_, DC_, DIM_, DIM_, DIM_, DC_, 1.f, nullptr, 1, 1, 0,0,0,0,0,0);
    gemm<1>(ckv, wuk, K,       BT_, DH_,  DC_, DC_, NH_*DC_, NH_*QKD_, 1.f, nullptr,
            NH_, NH_, 0,0, 0, DC_, 0, QKD_);
    gemm<1>(ckv, wuv, V,       BT_, DH_,  DC_, DC_, NH_*DC_, NH_*DH_,  1.f, nullptr,
            NH_, NH_, 0,0, 0, DC_, 0, DH_);
    gemm<1>(cq,  wuq, Q,       BT_, DH_,  DC_, DC_, NH_*DC_, NH_*QKD_, 1.f, nullptr,
            NH_, NH_, 0,0, 0, DC_, 0, QKD_);
    gemm<1>(cq,  wqr, Q + DH_, BT_, DRH_, DC_, DC_, NH_*DC_, NH_*QKD_, 1.f, nullptr,
            NH_, NH_, 0,0, 0, DC_, 0, QKD_);
    gemm<1>(h, wkr, kr, BT_, DRH_, DIM_, DIM_, DIM_, DRH_, 1.f, nullptr, 1, 1, 0,0,0,0,0,0);
    rope_q_k<<<BT_ * NH_, 32>>>(Q);
    rope_kr_k<<<BT_, 32>>>(kr, K);
    // logits (batched over b,h), scaled; causal block skip
    float scale = 1.0f / sqrtf((float)QKD_);
    gemm<1>(Q, K, S, T_, T_, QKD_, NH_*QKD_, NH_*QKD_, T_, scale, nullptr,
            B_*NH_, NH_,
            (long long)T_*NH_*QKD_, QKD_,
            (long long)T_*NH_*QKD_, QKD_,
            (long long)NH_*T_*T_, (long long)T_*T_,
            nullptr, nullptr, nullptr, nullptr, 0, /*causal=*/1);
    softmax_k<<<B_ * NH_ * T_, 256>>>(S);
    // out[l,k] = sum_t S[t,l] V[t,k]  (TN); skip K chunks with t < l (S==0 there)
    gemm<2>(S, V, O, T_, DH_, T_, T_, NH_*DH_, NH_*DH_, 1.f, nullptr,
            B_*NH_, NH_,
            (long long)NH_*T_*T_, (long long)T_*T_,
            (long long)T_*NH_*DH_, DH_,
            (long long)T_*NH_*DH_, DH_,
            nullptr, nullptr, nullptr, nullptr, 0, 0, /*causalAV=*/1);
    // attn projection + residual
    pack_wo_k<<<(DIM_*2048 + 255)/256, 256>>>(wo, Wo);
    gemm<1>(O, Wo, x1, BT_, DIM_, NH_*DH_, NH_*DH_, NH_*DH_, DIM_, 1.f, x,
            1, 1, 0,0,0,0,0,0);

    // ---- MoE ----
    rmsnorm_k<<<BT_, 256>>>(x1, ffn_w, xn);
    cudaMemsetAsync(cnt, 0, NE_ * sizeof(int));
    float* affOut = (out_size >= BT_*DIM_ + BT_*NE_) ? out + (long long)BT_*DIM_ : nullptr;
    gate_k<<<BT_, 256>>>(xn, gate_w, gate_b, affOut, cnt, tok, wt);
    // shared expert
    gemm<0>(xn, w1s, a1, BT_, MOESH_, DIM_, DIM_, MOESH_, MOESH_, 1.f, nullptr, 1,1,0,0,0,0,0,0);
    gemm<0>(xn, w3s, a3, BT_, MOESH_, DIM_, DIM_, MOESH_, MOESH_, 1.f, nullptr, 1,1,0,0,0,0,0,0);
    silumul_k<<<((BT_*MOESH_/4) + 255)/256, 256>>>((float4*)a1, (const float4*)a3,
                                                   (long long)BT_*MOESH_/4);
    gemm<0>(a1, w2s, out, BT_, DIM_, MOESH_, MOESH_, DIM_, DIM_, 1.f, x1, 1,1,0,0,0,0,0,0);
    // routed experts (top-4 only; gathered GEMMs with dynamic M, fused weighted scatter)
    gemm<0>(xn, w1r, h1, CAP_, MOE_, DIM_, DIM_, MOE_, MOE_, 1.f, nullptr,
            NE_, NE_, 0,0, 0, (long long)DIM_*MOE_, 0, (long long)CAP_*MOE_,
            cnt, tok, nullptr, nullptr, CAP_);
    gemm<0>(xn, w3r, h2, CAP_, MOE_, DIM_, DIM_, MOE_, MOE_, 1.f, nullptr,
            NE_, NE_, 0,0, 0, (long long)DIM_*MOE_, 0, (long long)CAP_*MOE_,
            cnt, tok, nullptr, nullptr, CAP_);
    silumul_routed_k<<<(((long long)NE_*CAP_*MOE_/4) + 255)/256, 256>>>(
        (float4*)h1, (const float4*)h2, cnt);
    gemm<0>(h1, w2r, out, CAP_, DIM_, MOE_, MOE_, DIM_, DIM_, 1.f, nullptr,
            NE_, NE_, 0, (long long)CAP_*MOE_, 0, (long long)MOE_*DIM_, 0, 0,
            cnt, nullptr, tok, wt, CAP_);
}

// round 6
// speedup vs baseline: 1.2441x; 1.0156x over previous
#include <cuda_runtime.h>
#include <cuda_bf16.h>
#include <math.h>
#include <stdint.h>

#define B_    2
#define T_    1024
#define BT_   2048
#define DIM_  2048
#define NH_   16
#define DH_   128
#define DRH_  64
#define DC_   512
#define NE_   16
#define TOPK_ 4
#define MOE_  1024
#define MOESH_ 2048
#define CAP_  2048
#define QKD_  192   // DH + DRH

// ---------------- scratch (static device globals; no runtime alloc) ----------
__device__ float g_h  [BT_*DIM_];
__device__ float g_ckv[BT_*DC_];
__device__ float g_cq [BT_*DC_];
__device__ float g_Q  [BT_*NH_*QKD_];
__device__ float g_K  [BT_*NH_*QKD_];
__device__ float g_V  [BT_*NH_*DH_];
__device__ float g_kr [BT_*DRH_];
__device__ float g_S  [(size_t)B_*NH_*T_*T_];
__device__ float g_O  [BT_*NH_*DH_];
__device__ float g_Wo [DIM_*NH_*DH_];
__device__ float g_x1 [BT_*DIM_];
__device__ float g_xn [BT_*DIM_];
__device__ float g_a1 [BT_*MOESH_];
__device__ float g_a3 [BT_*MOESH_];
__device__ float g_h1 [(size_t)NE_*CAP_*MOE_];
__device__ float g_h2 [(size_t)NE_*CAP_*MOE_];
__device__ int   g_cnt[NE_];
__device__ int   g_tok[NE_*CAP_];
__device__ float g_wt [NE_*CAP_];

// ---------------- 3xTF32 tensor-core GEMM (single-buffer BK=16, zero-fill) ----
// MODE 0: C = A(M,K) * B(K,N)      (NN)
// MODE 1: C = A(M,K) * B(N,K)^T    (NT)
// MODE 2: C = A(K,M)^T * B(K,N)    (TN)
struct GemmP {
    const float* A; const float* B; float* C; const float* res;
    int M, N, K, lda, ldb, ldc;
    float alpha;
    long long aO1, aO2, bO1, bO2, cO1, cO2;
    int zdiv, cap;
    const int* Mvec;    // per-z dynamic M (row count)
    const int* aRows;   // per-z row gather indices into A
    const int* cRows;   // per-z row scatter indices into C (atomicAdd)
    const float* wRow;  // per-row scatter weight
    int causal;         // MODE1 logits: skip blocks entirely above diagonal
    int causalAV;       // MODE2 AV: K loop starts at m0 (S lower-triangular)
};

__device__ __forceinline__ uint32_t f2t(float x) {
    uint32_t u; asm("cvt.rna.tf32.f32 %0, %1;" : "=r"(u) : "f"(x)); return u;
}

__device__ __forceinline__ void mma_tf32(float* c, const uint32_t* a, const uint32_t* b) {
    asm volatile("mma.sync.aligned.m16n8k8.row.col.f32.tf32.tf32.f32 "
        "{%0,%1,%2,%3}, {%4,%5,%6,%7}, {%8,%9}, {%0,%1,%2,%3};\n"
        : "+f"(c[0]), "+f"(c[1]), "+f"(c[2]), "+f"(c[3])
        : "r"(a[0]), "r"(a[1]), "r"(a[2]), "r"(a[3]), "r"(b[0]), "r"(b[1]));
}

template<int MODE>
__global__ __launch_bounds__(256, 2) void gemm_k(GemmP p) {
    __shared__ uint32_t sAh[16][136], sAl[16][136], sBh[16][136], sBl[16][136];

    int z = blockIdx.z, z1 = z / p.zdiv, z2 = z - z1 * p.zdiv;
    const float* A  = p.A + z1 * p.aO1 + z2 * p.aO2;
    const float* Bp = p.B + z1 * p.bO1 + z2 * p.bO2;
    float*       C  = p.C + z1 * p.cO1 + z2 * p.cO2;
    int M = p.Mvec ? p.Mvec[z] : p.M;
    int m0 = blockIdx.y * 128, n0 = blockIdx.x * 128;
    if (m0 >= M) return;
    if (MODE == 1 && p.causal && n0 >= m0 + 128) return;  // fully masked block
    int tid = threadIdx.x, lane = tid & 31, warp = tid >> 5;
    int wm = (warp & 1) << 6, wn = (warp >> 1) << 5;   // warp tile 64x32
    int gid = lane >> 2, tg = lane & 3;

    // ---- per-thread load setup (zero-fill out of range; never clamp) ----
    bool aValid[2]; const float* aPtr[2]; int aK[2], aM[2];
    bool bValid[2]; const float* bPtr[2]; int bK[2], bM[2];
#pragma unroll
    for (int s = 0; s < 2; s++) {
        int idx = tid + s * 256;
        if (MODE != 2) {                // A[row][k], rows of M; 128 rows x 16 k
            int r = m0 + (idx >> 2);
            aValid[s] = (r < M);
            long long ar = 0;
            if (aValid[s]) ar = p.aRows ? (long long)p.aRows[(long long)z * p.cap + r]
                                        : (long long)r;
            aPtr[s] = A + ar * (long long)p.lda + (idx & 3) * 4;
            aK[s] = (idx & 3) * 4;  aM[s] = idx >> 2;
        } else {                        // A[k][m]; 16 k x 128 m
            int m = m0 + (idx & 31) * 4;
            aValid[s] = (m < M);
            aPtr[s] = A + (long long)(idx >> 5) * p.lda + (aValid[s] ? m : 0);
            aK[s] = idx >> 5;       aM[s] = (idx & 31) * 4;
        }
        if (MODE == 1) {                // B[n][k]
            int cl = n0 + (idx >> 2);
            bValid[s] = (cl < p.N);
            bPtr[s] = Bp + (bValid[s] ? (long long)cl * p.ldb : 0) + (idx & 3) * 4;
            bK[s] = (idx & 3) * 4;  bM[s] = idx >> 2;
        } else {                        // B[k][n]
            int n = n0 + (idx & 31) * 4;
            bValid[s] = (n < p.N);
            bPtr[s] = Bp + (long long)(idx >> 5) * p.ldb + (bValid[s] ? n : 0);
            bK[s] = idx >> 5;       bM[s] = (idx & 31) * 4;
        }
    }

    float acc[4][4][4];
#pragma unroll
    for (int mi = 0; mi < 4; mi++)
#pragma unroll
        for (int ni = 0; ni < 4; ni++)
#pragma unroll
            for (int q = 0; q < 4; q++) acc[mi][ni][q] = 0.f;

    const float4 z4 = make_float4(0.f, 0.f, 0.f, 0.f);
    int kStart = (MODE == 2 && p.causalAV) ? (m0 & ~15) : 0;
    int nIter = (p.K - kStart) >> 4;

    float4 va[2], vb[2];
#pragma unroll
    for (int s = 0; s < 2; s++) {
        long long ka = (MODE == 2) ? (long long)kStart * p.lda : (long long)kStart;
        long long kb = (MODE == 1) ? (long long)kStart : (long long)kStart * p.ldb;
        va[s] = aValid[s] ? *(const float4*)(aPtr[s] + ka) : z4;
        vb[s] = bValid[s] ? *(const float4*)(bPtr[s] + kb) : z4;
    }

    for (int it = 0; it < nIter; it++) {
        // store current 16-K chunk into smem (hi/lo split)
#pragma unroll
        for (int s = 0; s < 2; s++) {
            const float* a4 = (const float*)&va[s];
            const float* b4 = (const float*)&vb[s];
#pragma unroll
            for (int j = 0; j < 4; j++) {
                uint32_t hu = f2t(a4[j]);
                uint32_t lu = f2t(a4[j] - __uint_as_float(hu));
                if (MODE == 2) { sAh[aK[s]][aM[s] + j] = hu; sAl[aK[s]][aM[s] + j] = lu; }
                else           { sAh[aK[s] + j][aM[s]] = hu; sAl[aK[s] + j][aM[s]] = lu; }
                uint32_t hb = f2t(b4[j]);
                uint32_t lb = f2t(b4[j] - __uint_as_float(hb));
                if (MODE == 1) { sBh[bK[s] + j][bM[s]] = hb; sBl[bK[s] + j][bM[s]] = lb; }
                else           { sBh[bK[s]][bM[s] + j] = hb; sBl[bK[s]][bM[s] + j] = lb; }
            }
        }
        __syncthreads();

        // prefetch next chunk (overlaps with MMAs below)
        float4 na[2] = {z4, z4}, nb[2] = {z4, z4};
        if (it + 1 < nIter) {
            int kNext = kStart + (it + 1) * 16;
            long long ka = (MODE == 2) ? (long long)kNext * p.lda : (long long)kNext;
            long long kb = (MODE == 1) ? (long long)kNext : (long long)kNext * p.ldb;
#pragma unroll
            for (int s = 0; s < 2; s++) {
                if (aValid[s]) na[s] = *(const float4*)(aPtr[s] + ka);
                if (bValid[s]) nb[s] = *(const float4*)(bPtr[s] + kb);
            }
        }

        // two k=8 sub-chunks; B fragments staged once, A streamed per mi
#pragma unroll
        for (int kk = 0; kk < 16; kk += 8) {
            uint32_t bh[4][2], bl[4][2];
#pragma unroll
            for (int ni = 0; ni < 4; ni++) {
                int nb2 = wn + ni * 8;
                bh[ni][0] = sBh[kk + tg    ][nb2 + gid];
                bh[ni][1] = sBh[kk + tg + 4][nb2 + gid];
                bl[ni][0] = sBl[kk + tg    ][nb2 + gid];
                bl[ni][1] = sBl[kk + tg + 4][nb2 + gid];
            }
#pragma unroll
            for (int mi = 0; mi < 4; mi++) {
                int mb = wm + mi * 16;
                uint32_t ah[4], al[4];
                ah[0] = sAh[kk + tg    ][mb + gid];
                ah[1] = sAh[kk + tg    ][mb + gid + 8];
                ah[2] = sAh[kk + tg + 4][mb + gid];
                ah[3] = sAh[kk + tg + 4][mb + gid + 8];
                al[0] = sAl[kk + tg    ][mb + gid];
                al[1] = sAl[kk + tg    ][mb + gid + 8];
                al[2] = sAl[kk + tg + 4][mb + gid];
                al[3] = sAl[kk + tg + 4][mb + gid + 8];
#pragma unroll
                for (int ni = 0; ni < 4; ni++)
                    mma_tf32(acc[mi][ni], ah, bh[ni]);
#pragma unroll
                for (int ni = 0; ni < 4; ni++)
                    mma_tf32(acc[mi][ni], al, bh[ni]);
#pragma unroll
                for (int ni = 0; ni < 4; ni++)
                    mma_tf32(acc[mi][ni], ah, bl[ni]);
            }
        }
        __syncthreads();
#pragma unroll
        for (int s = 0; s < 2; s++) { va[s] = na[s]; vb[s] = nb[s]; }
    }

    // epilogue: c0,c1 -> row gid, cols 2tg,2tg+1 ; c2,c3 -> row gid+8
#pragma unroll
    for (int mi = 0; mi < 4; mi++) {
#pragma unroll
        for (int half = 0; half < 2; half++) {
            int m = m0 + wm + mi * 16 + gid + half * 8;
            if (m >= M) continue;
            long long crow; float w = p.alpha;
            if (p.cRows) {
                crow = (long long)p.cRows[(long long)z * p.cap + m] * p.ldc;
                w *= p.wRow[(long long)z * p.cap + m];
            } else {
                crow = (long long)m * p.ldc;
            }
#pragma unroll
            for (int ni = 0; ni < 4; ni++) {
                int n = n0 + wn + ni * 8 + tg * 2;
                if (n >= p.N) continue;
                float v0 = acc[mi][ni][half * 2 + 0] * w;
                float v1 = acc[mi][ni][half * 2 + 1] * w;
                if (p.cRows) {
                    atomicAdd(&C[crow + n],     v0);
                    atomicAdd(&C[crow + n + 1], v1);
                } else {
                    if (p.res) { v0 += p.res[crow + n]; v1 += p.res[crow + n + 1]; }
                    C[crow + n]     = v0;
                    C[crow + n + 1] = v1;
                }
            }
        }
    }
}

// ---------------- small fused kernels -----------------------------------------
__global__ void rmsnorm_k(const float* __restrict__ x, const float* __restrict__ w,
                          float* __restrict__ o) {
    int r = blockIdx.x;
    const float* xr = x + (long long)r * DIM_;
    float s = 0.f;
    for (int d = threadIdx.x; d < DIM_; d += 256) { float v = xr[d]; s += v * v; }
    __shared__ float red[256];
    red[threadIdx.x] = s; __syncthreads();
    for (int off = 128; off; off >>= 1) {
        if (threadIdx.x < off) red[threadIdx.x] += red[threadIdx.x + off];
        __syncthreads();
    }
    float inv = rsqrtf(red[0] / (float)DIM_ + 1e-6f);
    float* orow = o + (long long)r * DIM_;
    for (int d = threadIdx.x; d < DIM_; d += 256) orow[d] = w[d] * xr[d] * inv;
}

__device__ __forceinline__ void rope_cs(int t, int j, float& c, float& s) {
    float freq = 1.0f / powf(10000.0f, (float)(2 * j) / (float)DRH_);
    float ang = (float)t * freq;
    sincosf(ang, &s, &c);
}

__global__ void rope_q_k(float* __restrict__ Q) {
    int idx = blockIdx.x;            // bt*NH + h
    int bt = idx / NH_;
    int t = bt % T_;
    int j = threadIdx.x;             // 0..31
    float* base = Q + (long long)idx * QKD_ + DH_;
    float re = base[j], im = base[32 + j];
    float c, s; rope_cs(t, j, c, s);
    base[j]      = re * c - im * s;
    base[32 + j] = re * s + im * c;
}

__global__ void rope_kr_k(const float* __restrict__ kr, float* __restrict__ Kb) {
    int bt = blockIdx.x;
    int t = bt % T_;
    int j = threadIdx.x;             // 0..31
    float re = kr[bt * DRH_ + j], im = kr[bt * DRH_ + 32 + j];
    float c, s; rope_cs(t, j, c, s);
    float o1 = (re * c - im * s) / (float)NH_;
    float o2 = (re * s + im * c) / (float)NH_;
    for (int h = 0; h < NH_; h++) {
        float* base = Kb + ((long long)bt * NH_ + h) * QKD_ + DH_;
        base[j] = o1; base[32 + j] = o2;
    }
}

__global__ void softmax_k(float* __restrict__ S) {
    long long r = blockIdx.x;        // (b,h,t) row
    int t = (int)(r & (T_ - 1));
    float* row = S + r * (long long)T_;
    int n = t + 1;
    __shared__ float red[256];
    int tid = threadIdx.x;
    float mx = -INFINITY;
    for (int l = tid; l < n; l += 256) mx = fmaxf(mx, row[l]);
    red[tid] = mx; __syncthreads();
    for (int off = 128; off; off >>= 1) {
        if (tid < off) red[tid] = fmaxf(red[tid], red[tid + off]);
        __syncthreads();
    }
    mx = red[0]; __syncthreads();
    float sum = 0.f;
    for (int l = tid; l < n; l += 256) { float e = expf(row[l] - mx); row[l] = e; sum += e; }
    red[tid] = sum; __syncthreads();
    for (int off = 128; off; off >>= 1) {
        if (tid < off) red[tid] += red[tid + off];
        __syncthreads();
    }
    float inv = 1.f / red[0];
    for (int l = tid; l < T_; l += 256) row[l] = (l < n) ? row[l] * inv : 0.f;
}

__global__ void pack_wo_k(const float* __restrict__ wo, float* __restrict__ out) {
    long long i = (long long)blockIdx.x * 256 + threadIdx.x;  // d*2048 + h*128 + k
    if (i >= (long long)DIM_ * 2048) return;
    int d = (int)(i >> 11);
    int r = (int)(i & 2047);
    int h = r >> 7, k = r & 127;
    out[i] = wo[(long long)d * 2048 + k * NH_ + h];
}

__global__ void gate_k(const float* __restrict__ xn, const float* __restrict__ gw,
                       const float* __restrict__ gb, float* affOut,
                       int* __restrict__ cnt, int* __restrict__ tok,
                       float* __restrict__ wt) {
    int bt = blockIdx.x;
    __shared__ float xrow[DIM_];
    __shared__ float aff[NE_];
    int tid = threadIdx.x;
    for (int d = tid; d < DIM_; d += 256) xrow[d] = xn[(long long)bt * DIM_ + d];
    __syncthreads();
    int w = tid >> 5, lane = tid & 31;
    for (int e = w; e < NE_; e += 8) {
        float s = 0.f;
        const float* gr = gw + (long long)e * DIM_;
        for (int d = lane; d < DIM_; d += 32) s += xrow[d] * gr[d];
        for (int o = 16; o; o >>= 1) s += __shfl_xor_sync(0xffffffffu, s, o);
        if (lane == 0) aff[e] = 1.f / (1.f + expf(-s)) + gb[e];
    }
    __syncthreads();
    if (tid == 0) {
        if (affOut) for (int e = 0; e < NE_; e++) affOut[(long long)bt * NE_ + e] = aff[e];
        bool used[NE_] = {};
        float wv[TOPK_]; int wi[TOPK_]; float sum = 0.f;
        for (int k = 0; k < TOPK_; k++) {
            float best = -1e30f; int bi = 0;
            for (int e = 0; e < NE_; e++)
                if (!used[e] && aff[e] > best) { best = aff[e]; bi = e; }
            used[bi] = true; wv[k] = best; wi[k] = bi; sum += best;
        }
        for (int k = 0; k < TOPK_; k++) {
            int e = wi[k];
            int pos = atomicAdd(&cnt[e], 1);
            tok[e * CAP_ + pos] = bt;
            wt [e * CAP_ + pos] = wv[k] / sum;
        }
    }
}

__global__ void silumul_k(float4* __restrict__ a, const float4* __restrict__ b, long long n4) {
    long long i = (long long)blockIdx.x * 256 + threadIdx.x;
    if (i >= n4) return;
    float4 x = a[i], y = b[i];
    x.x *= y.x; x.y *= y.y; x.z *= y.z; x.w *= y.w;
    x.x = x.x / (1.f + expf(-x.x));
    x.y = x.y / (1.f + expf(-x.y));
    x.z = x.z / (1.f + expf(-x.z));
    x.w = x.w / (1.f + expf(-x.w));
    a[i] = x;
}

__global__ void silumul_routed_k(float4* __restrict__ a, const float4* __restrict__ b,
                                 const int* __restrict__ cnt) {
    long long i = (long long)blockIdx.x * 256 + threadIdx.x;   // NE*CAP*MOE/4
    long long el = i << 2;
    int e = (int)(el >> 21);                // CAP_*MOE_ = 2^21
    int ri = (int)((el >> 10) & (CAP_ - 1));
    if (ri >= cnt[e]) return;
    float4 x = a[i], y = b[i];
    x.x *= y.x; x.y *= y.y; x.z *= y.z; x.w *= y.w;
    x.x = x.x / (1.f + expf(-x.x));
    x.y = x.y / (1.f + expf(-x.y));
    x.z = x.z / (1.f + expf(-x.z));
    x.w = x.w / (1.f + expf(-x.w));
    a[i] = x;
}

// ---------------- host-side launch helpers ------------------------------------
template<int MODE>
static void gemm(const float* A, const float* B, float* C, int M, int N, int K,
                 int lda, int ldb, int ldc, float alpha, const float* res,
                 int nz, int zdiv,
                 long long a1, long long a2, long long b1, long long b2,
                 long long c1, long long c2,
                 const int* Mvec = nullptr, const int* aRows = nullptr,
                 const int* cRows = nullptr, const float* wRow = nullptr,
                 int cap = 0, int causal = 0, int causalAV = 0) {
    GemmP p;
    p.A = A; p.B = B; p.C = C; p.res = res;
    p.M = M; p.N = N; p.K = K; p.lda = lda; p.ldb = ldb; p.ldc = ldc;
    p.alpha = alpha;
    p.aO1 = a1; p.aO2 = a2; p.bO1 = b1; p.bO2 = b2; p.cO1 = c1; p.cO2 = c2;
    p.zdiv = zdiv; p.cap = cap;
    p.Mvec = Mvec; p.aRows = aRows; p.cRows = cRows; p.wRow = wRow;
    p.causal = causal; p.causalAV = causalAV;
    dim3 g((N + 127) / 128, (M + 127) / 128, nz);
    gemm_k<MODE><<<g, 256>>>(p);
}

extern "C" void kernel_launch(void* const* d_in, const int* in_sizes, int n_in,
                              void* d_out, int out_size) {
    const float* x      = (const float*)d_in[0];
    const float* attn_w = (const float*)d_in[3];
    const float* ffn_w  = (const float*)d_in[4];
    const float* gate_w = (const float*)d_in[5];
    const float* gate_b = (const float*)d_in[6];
    const float* w1s    = (const float*)d_in[7];
    const float* w2s    = (const float*)d_in[8];
    const float* w3s    = (const float*)d_in[9];
    const float* w1r    = (const float*)d_in[10];
    const float* w2r    = (const float*)d_in[11];
    const float* w3r    = (const float*)d_in[12];
    const float* wdkv   = (const float*)d_in[13];
    const float* wuk    = (const float*)d_in[14];
    const float* wuv    = (const float*)d_in[15];
    const float* wdq    = (const float*)d_in[16];
    const float* wuq    = (const float*)d_in[17];
    const float* wqr    = (const float*)d_in[18];
    const float* wkr    = (const float*)d_in[19];
    const float* wo     = (const float*)d_in[20];
    float* out = (float*)d_out;

    float *h, *ckv, *cq, *Q, *K, *V, *kr, *S, *O, *Wo, *x1, *xn, *a1, *a3, *h1, *h2, *wt;
    int *cnt, *tok;
    cudaGetSymbolAddress((void**)&h,   g_h);
    cudaGetSymbolAddress((void**)&ckv, g_ckv);
    cudaGetSymbolAddress((void**)&cq,  g_cq);
    cudaGetSymbolAddress((void**)&Q,   g_Q);
    cudaGetSymbolAddress((void**)&K,   g_K);
    cudaGetSymbolAddress((void**)&V,   g_V);
    cudaGetSymbolAddress((void**)&kr,  g_kr);
    cudaGetSymbolAddress((void**)&S,   g_S);
    cudaGetSymbolAddress((void**)&O,   g_O);
    cudaGetSymbolAddress((void**)&Wo,  g_Wo);
    cudaGetSymbolAddress((void**)&x1,  g_x1);
    cudaGetSymbolAddress((void**)&xn,  g_xn);
    cudaGetSymbolAddress((void**)&a1,  g_a1);
    cudaGetSymbolAddress((void**)&a3,  g_a3);
    cudaGetSymbolAddress((void**)&h1,  g_h1);
    cudaGetSymbolAddress((void**)&h2,  g_h2);
    cudaGetSymbolAddress((void**)&cnt, g_cnt);
    cudaGetSymbolAddress((void**)&tok, g_tok);
    cudaGetSymbolAddress((void**)&wt,  g_wt);

    // ---- attention ----
    rmsnorm_k<<<BT_, 256>>>(x, attn_w, h);
    gemm<1>(h, wdkv, ckv, BT_, DC_, DIM_, DIM_, DIM_, DC_, 1.f, nullptr, 1, 1, 0,0,0,0,0,0);
    gemm<1>(h, wdq,  cq,  BT_, DC_, DIM_, DIM_, DIM_, DC_, 1.f, nullptr, 1, 1, 0,0,0,0,0,0);
    gemm<1>(ckv, wuk, K,       BT_, DH_,  DC_, DC_, NH_*DC_, NH_*QKD_, 1.f, nullptr,
            NH_, NH_, 0,0, 0, DC_, 0, QKD_);
    gemm<1>(ckv, wuv, V,       BT_, DH_,  DC_, DC_, NH_*DC_, NH_*DH_,  1.f, nullptr,
            NH_, NH_, 0,0, 0, DC_, 0, DH_);
    gemm<1>(cq,  wuq, Q,       BT_, DH_,  DC_, DC_, NH_*DC_, NH_*QKD_, 1.f, nullptr,
            NH_, NH_, 0,0, 0, DC_, 0, QKD_);
    gemm<1>(cq,  wqr, Q + DH_, BT_, DRH_, DC_, DC_, NH_*DC_, NH_*QKD_, 1.f, nullptr,
            NH_, NH_, 0,0, 0, DC_, 0, QKD_);
    gemm<1>(h, wkr, kr, BT_, DRH_, DIM_, DIM_, DIM_, DRH_, 1.f, nullptr, 1, 1, 0,0,0,0,0,0);
    rope_q_k<<<BT_ * NH_, 32>>>(Q);
    rope_kr_k<<<BT_, 32>>>(kr, K);
    // logits (batched over b,h), scaled; causal block skip
    float scale = 1.0f / sqrtf((float)QKD_);
    gemm<1>(Q, K, S, T_, T_, QKD_, NH_*QKD_, NH_*QKD_, T_, scale, nullptr,
            B_*NH_, NH_,
            (long long)T_*NH_*QKD_, QKD_,
            (long long)T_*NH_*QKD_, QKD_,
            (long long)NH_*T_*T_, (long long)T_*T_,
            nullptr, nullptr, nullptr, nullptr, 0, /*causal=*/1);
    softmax_k<<<B_ * NH_ * T_, 256>>>(S);
    // out[l,k] = sum_t S[t,l] V[t,k]  (TN); skip K chunks with t < l (S==0 there)
    gemm<2>(S, V, O, T_, DH_, T_, T_, NH_*DH_, NH_*DH_, 1.f, nullptr,
            B_*NH_, NH_,
            (long long)NH_*T_*T_, (long long)T_*T_,
            (long long)T_*NH_*DH_, DH_,
            (long long)T_*NH_*DH_, DH_,
            nullptr, nullptr, nullptr, nullptr, 0, 0, /*causalAV=*/1);
    // attn projection + residual
    pack_wo_k<<<(DIM_*2048 + 255)/256, 256>>>(wo, Wo);
    gemm<1>(O, Wo, x1, BT_, DIM_, NH_*DH_, NH_*DH_, NH_*DH_, DIM_, 1.f, x,
            1, 1, 0,0,0,0,0,0);

    // ---- MoE ----
    rmsnorm_k<<<BT_, 256>>>(x1, ffn_w, xn);
    cudaMemsetAsync(cnt, 0, NE_ * sizeof(int));
    float* affOut = (out_size >= BT_*DIM_ + BT_*NE_) ? out + (long long)BT_*DIM_ : nullptr;
    gate_k<<<BT_, 256>>>(xn, gate_w, gate_b, affOut, cnt, tok, wt);
    // shared expert
    gemm<0>(xn, w1s, a1, BT_, MOESH_, DIM_, DIM_, MOESH_, MOESH_, 1.f, nullptr, 1,1,0,0,0,0,0,0);
    gemm<0>(xn, w3s, a3, BT_, MOESH_, DIM_, DIM_, MOESH_, MOESH_, 1.f, nullptr, 1,1,0,0,0,0,0,0);
    silumul_k<<<((BT_*MOESH_/4) + 255)/256, 256>>>((float4*)a1, (const float4*)a3,
                                                   (long long)BT_*MOESH_/4);
    gemm<0>(a1, w2s, out, BT_, DIM_, MOESH_, MOESH_, DIM_, DIM_, 1.f, x1, 1,1,0,0,0,0,0,0);
    // routed experts (top-4 only; gathered GEMMs with dynamic M, fused weighted scatter)
    gemm<0>(xn, w1r, h1, CAP_, MOE_, DIM_, DIM_, MOE_, MOE_, 1.f, nullptr,
            NE_, NE_, 0,0, 0, (long long)DIM_*MOE_, 0, (long long)CAP_*MOE_,
            cnt, tok, nullptr, nullptr, CAP_);
    gemm<0>(xn, w3r, h2, CAP_, MOE_, DIM_, DIM_, MOE_, MOE_, 1.f, nullptr,
            NE_, NE_, 0,0, 0, (long long)DIM_*MOE_, 0, (long long)CAP_*MOE_,
            cnt, tok, nullptr, nullptr, CAP_);
    silumul_routed_k<<<(((long long)NE_*CAP_*MOE_/4) + 255)/256, 256>>>(
        (float4*)h1, (const float4*)h2, cnt);
    gemm<0>(h1, w2r, out, CAP_, DIM_, MOE_, MOE_, DIM_, DIM_, 1.f, nullptr,
            NE_, NE_, 0, (long long)CAP_*MOE_, 0, (long long)MOE_*DIM_, 0, 0,
            cnt, nullptr, tok, wt, CAP_);
}

// round 7
// speedup vs baseline: 1.3123x; 1.0549x over previous
#include <cuda_runtime.h>
#include <cuda_bf16.h>
#include <math.h>
#include <stdint.h>

#define B_    2
#define T_    1024
#define BT_   2048
#define DIM_  2048
#define NH_   16
#define DH_   128
#define DRH_  64
#define DC_   512
#define NE_   16
#define TOPK_ 4
#define MOE_  1024
#define MOESH_ 2048
#define CAP_  2048
#define QKD_  192   // DH + DRH

// ---------------- scratch (static device globals; no runtime alloc) ----------
__device__ float g_h  [BT_*DIM_];
__device__ float g_ckv[BT_*DC_];
__device__ float g_cq [BT_*DC_];
__device__ float g_Q  [BT_*NH_*QKD_];
__device__ float g_K  [BT_*NH_*QKD_];
__device__ float g_V  [BT_*NH_*DH_];
__device__ float g_kr [BT_*DRH_];
__device__ float g_S  [(size_t)B_*NH_*T_*T_];
__device__ float g_O  [BT_*NH_*DH_];
__device__ float g_Wo [DIM_*NH_*DH_];
__device__ float g_x1 [BT_*DIM_];
__device__ float g_xn [BT_*DIM_];
__device__ float g_a1 [BT_*MOESH_];
__device__ float g_a3 [BT_*MOESH_];
__device__ float g_h1 [(size_t)NE_*CAP_*MOE_];
__device__ float g_h2 [(size_t)NE_*CAP_*MOE_];
__device__ int   g_cnt[NE_];
__device__ int   g_tok[NE_*CAP_];
__device__ float g_wt [NE_*CAP_];

// ---------------- 3xTF32 tensor-core GEMM -------------------------------------
// Double-buffered BK=8, hi/lo packed as uint2 (LDS.64/STS.64), zero-fill.
// MODE 0: C = A(M,K) * B(K,N)      (NN)
// MODE 1: C = A(M,K) * B(N,K)^T    (NT)
// MODE 2: C = A(K,M)^T * B(K,N)    (TN)
struct GemmP {
    const float* A; const float* B; float* C; const float* res;
    int M, N, K, lda, ldb, ldc;
    float alpha;
    long long aO1, aO2, bO1, bO2, cO1, cO2;
    int zdiv, cap;
    const int* Mvec;    // per-z dynamic M (row count)
    const int* aRows;   // per-z row gather indices into A
    const int* cRows;   // per-z row scatter indices into C (atomicAdd)
    const float* wRow;  // per-row scatter weight
    int causal;         // MODE1 logits: skip blocks entirely above diagonal
    int causalAV;       // MODE2 AV: K loop starts at m0 (S lower-triangular)
};

__device__ __forceinline__ uint32_t f2t(float x) {
    uint32_t u; asm("cvt.rna.tf32.f32 %0, %1;" : "=r"(u) : "f"(x)); return u;
}

__device__ __forceinline__ uint2 split_hl(float x) {
    uint32_t h = f2t(x);
    uint32_t l = f2t(x - __uint_as_float(h));
    return make_uint2(h, l);
}

__device__ __forceinline__ void mma_tf32(float* c, const uint32_t* a, const uint32_t* b) {
    asm volatile("mma.sync.aligned.m16n8k8.row.col.f32.tf32.tf32.f32 "
        "{%0,%1,%2,%3}, {%4,%5,%6,%7}, {%8,%9}, {%0,%1,%2,%3};\n"
        : "+f"(c[0]), "+f"(c[1]), "+f"(c[2]), "+f"(c[3])
        : "r"(a[0]), "r"(a[1]), "r"(a[2]), "r"(a[3]), "r"(b[0]), "r"(b[1]));
}

template<int MODE>
__global__ __launch_bounds__(256, 2) void gemm_k(GemmP p) {
    __shared__ uint2 sA[2][8][132];   // [buf][k][m] = (hi, lo)
    __shared__ uint2 sB[2][8][132];   // [buf][k][n]

    int z = blockIdx.z, z1 = z / p.zdiv, z2 = z - z1 * p.zdiv;
    const float* A  = p.A + z1 * p.aO1 + z2 * p.aO2;
    const float* Bp = p.B + z1 * p.bO1 + z2 * p.bO2;
    float*       C  = p.C + z1 * p.cO1 + z2 * p.cO2;
    int M = p.Mvec ? p.Mvec[z] : p.M;
    int m0 = blockIdx.y * 128, n0 = blockIdx.x * 128;
    if (m0 >= M) return;
    if (MODE == 1 && p.causal && n0 >= m0 + 128) return;  // fully masked block
    int tid = threadIdx.x, lane = tid & 31, warp = tid >> 5;
    int wm = (warp & 1) << 6, wn = (warp >> 1) << 5;   // warp tile 64x32
    int gid = lane >> 2, tg = lane & 3;

    // ---- per-thread load setup (zero-fill out of range; never clamp) ----
    // BK=8: A tile = 128 rows x 8 k = 256 float4, one per thread. Same for B.
    bool aValid; const float* aPtr; int aK, aM;
    if (MODE != 2) {                    // A[row][k]: row = tid>>1, kq = tid&1
        int r = m0 + (tid >> 1);
        aValid = (r < M);
        long long ar = 0;
        if (aValid) ar = p.aRows ? (long long)p.aRows[(long long)z * p.cap + r]
                                 : (long long)r;
        aPtr = A + ar * (long long)p.lda + (tid & 1) * 4;
        aK = (tid & 1) * 4;  aM = tid >> 1;
    } else {                            // A[k][m]: k = tid>>5, m = (tid&31)*4
        int m = m0 + (tid & 31) * 4;
        aValid = (m < M);
        aPtr = A + (long long)(tid >> 5) * p.lda + (aValid ? m : 0);
        aK = tid >> 5;       aM = (tid & 31) * 4;
    }
    bool bValid; const float* bPtr; int bK, bM;
    if (MODE == 1) {                    // B[n][k]
        int cl = n0 + (tid >> 1);
        bValid = (cl < p.N);
        bPtr = Bp + (bValid ? (long long)cl * p.ldb : 0) + (tid & 1) * 4;
        bK = (tid & 1) * 4;  bM = tid >> 1;
    } else {                            // B[k][n]
        int n = n0 + (tid & 31) * 4;
        bValid = (n < p.N);
        bPtr = Bp + (long long)(tid >> 5) * p.ldb + (bValid ? n : 0);
        bK = tid >> 5;       bM = (tid & 31) * 4;
    }

    float acc[4][4][4];
#pragma unroll
    for (int mi = 0; mi < 4; mi++)
#pragma unroll
        for (int ni = 0; ni < 4; ni++)
#pragma unroll
            for (int q = 0; q < 4; q++) acc[mi][ni][q] = 0.f;

    const float4 z4 = make_float4(0.f, 0.f, 0.f, 0.f);
    int kStart = (MODE == 2 && p.causalAV) ? m0 : 0;   // m0 % 8 == 0
    int nIter = (p.K - kStart) >> 3;

    auto loadG = [&](int k, float4& oa, float4& ob) {
        long long ka = (MODE == 2) ? (long long)k * p.lda : (long long)k;
        long long kb = (MODE == 1) ? (long long)k : (long long)k * p.ldb;
        oa = aValid ? *(const float4*)(aPtr + ka) : z4;
        ob = bValid ? *(const float4*)(bPtr + kb) : z4;
    };
    auto storeS = [&](int buf, const float4& ia, const float4& ib) {
        const float* a4 = (const float*)&ia;
        const float* b4 = (const float*)&ib;
#pragma unroll
        for (int j = 0; j < 4; j++) {
            if (MODE == 2) sA[buf][aK][aM + j] = split_hl(a4[j]);
            else           sA[buf][aK + j][aM] = split_hl(a4[j]);
            if (MODE == 1) sB[buf][bK + j][bM] = split_hl(b4[j]);
            else           sB[buf][bK][bM + j] = split_hl(b4[j]);
        }
    };

    float4 va, vb;
    loadG(kStart, va, vb);
    storeS(0, va, vb);
    __syncthreads();

    for (int it = 0; it < nIter; it++) {
        int cur = it & 1;
        // prefetch next chunk early (hidden under MMA phase)
        float4 na = z4, nb = z4;
        if (it + 1 < nIter) loadG(kStart + (it + 1) * 8, na, nb);

        // fragments via 64-bit loads (hi,lo pair per LDS)
        uint2 vB0[4], vB1[4];
#pragma unroll
        for (int ni = 0; ni < 4; ni++) {
            int nb2 = wn + ni * 8 + gid;
            vB0[ni] = sB[cur][tg    ][nb2];
            vB1[ni] = sB[cur][tg + 4][nb2];
        }
#pragma unroll
        for (int mi = 0; mi < 4; mi++) {
            int mb = wm + mi * 16 + gid;
            uint2 a0 = sA[cur][tg    ][mb];
            uint2 a1 = sA[cur][tg    ][mb + 8];
            uint2 a2 = sA[cur][tg + 4][mb];
            uint2 a3 = sA[cur][tg + 4][mb + 8];
            uint32_t ah[4] = {a0.x, a1.x, a2.x, a3.x};
            uint32_t al[4] = {a0.y, a1.y, a2.y, a3.y};
#pragma unroll
            for (int ni = 0; ni < 4; ni++) {
                uint32_t bh[2] = {vB0[ni].x, vB1[ni].x};
                mma_tf32(acc[mi][ni], ah, bh);
            }
#pragma unroll
            for (int ni = 0; ni < 4; ni++) {
                uint32_t bh[2] = {vB0[ni].x, vB1[ni].x};
                mma_tf32(acc[mi][ni], al, bh);
            }
#pragma unroll
            for (int ni = 0; ni < 4; ni++) {
                uint32_t bl[2] = {vB0[ni].y, vB1[ni].y};
                mma_tf32(acc[mi][ni], ah, bl);
            }
        }

        // store next chunk into other buffer (overlaps other warps' MMAs)
        if (it + 1 < nIter) storeS(cur ^ 1, na, nb);
        __syncthreads();
    }

    // epilogue: c0,c1 -> row gid, cols 2tg,2tg+1 ; c2,c3 -> row gid+8
#pragma unroll
    for (int mi = 0; mi < 4; mi++) {
#pragma unroll
        for (int half = 0; half < 2; half++) {
            int m = m0 + wm + mi * 16 + gid + half * 8;
            if (m >= M) continue;
            long long crow; float w = p.alpha;
            if (p.cRows) {
                crow = (long long)p.cRows[(long long)z * p.cap + m] * p.ldc;
                w *= p.wRow[(long long)z * p.cap + m];
            } else {
                crow = (long long)m * p.ldc;
            }
#pragma unroll
            for (int ni = 0; ni < 4; ni++) {
                int n = n0 + wn + ni * 8 + tg * 2;
                if (n >= p.N) continue;
                float v0 = acc[mi][ni][half * 2 + 0] * w;
                float v1 = acc[mi][ni][half * 2 + 1] * w;
                if (p.cRows) {
                    atomicAdd(&C[crow + n],     v0);
                    atomicAdd(&C[crow + n + 1], v1);
                } else {
                    if (p.res) { v0 += p.res[crow + n]; v1 += p.res[crow + n + 1]; }
                    C[crow + n]     = v0;
                    C[crow + n + 1] = v1;
                }
            }
        }
    }
}

// ---------------- small fused kernels -----------------------------------------
__global__ void rmsnorm_k(const float* __restrict__ x, const float* __restrict__ w,
                          float* __restrict__ o) {
    int r = blockIdx.x;
    const float* xr = x + (long long)r * DIM_;
    float s = 0.f;
    for (int d = threadIdx.x; d < DIM_; d += 256) { float v = xr[d]; s += v * v; }
    __shared__ float red[256];
    red[threadIdx.x] = s; __syncthreads();
    for (int off = 128; off; off >>= 1) {
        if (threadIdx.x < off) red[threadIdx.x] += red[threadIdx.x + off];
        __syncthreads();
    }
    float inv = rsqrtf(red[0] / (float)DIM_ + 1e-6f);
    float* orow = o + (long long)r * DIM_;
    for (int d = threadIdx.x; d < DIM_; d += 256) orow[d] = w[d] * xr[d] * inv;
}

__device__ __forceinline__ void rope_cs(int t, int j, float& c, float& s) {
    float freq = 1.0f / powf(10000.0f, (float)(2 * j) / (float)DRH_);
    float ang = (float)t * freq;
    sincosf(ang, &s, &c);
}

__global__ void rope_q_k(float* __restrict__ Q) {
    int idx = blockIdx.x;            // bt*NH + h
    int bt = idx / NH_;
    int t = bt % T_;
    int j = threadIdx.x;             // 0..31
    float* base = Q + (long long)idx * QKD_ + DH_;
    float re = base[j], im = base[32 + j];
    float c, s; rope_cs(t, j, c, s);
    base[j]      = re * c - im * s;
    base[32 + j] = re * s + im * c;
}

__global__ void rope_kr_k(const float* __restrict__ kr, float* __restrict__ Kb) {
    int bt = blockIdx.x;
    int t = bt % T_;
    int j = threadIdx.x;             // 0..31
    float re = kr[bt * DRH_ + j], im = kr[bt * DRH_ + 32 + j];
    float c, s; rope_cs(t, j, c, s);
    float o1 = (re * c - im * s) / (float)NH_;
    float o2 = (re * s + im * c) / (float)NH_;
    for (int h = 0; h < NH_; h++) {
        float* base = Kb + ((long long)bt * NH_ + h) * QKD_ + DH_;
        base[j] = o1; base[32 + j] = o2;
    }
}

__global__ void softmax_k(float* __restrict__ S) {
    long long r = blockIdx.x;        // (b,h,t) row
    int t = (int)(r & (T_ - 1));
    float* row = S + r * (long long)T_;
    int n = t + 1;
    __shared__ float red[256];
    int tid = threadIdx.x;
    float mx = -INFINITY;
    for (int l = tid; l < n; l += 256) mx = fmaxf(mx, row[l]);
    red[tid] = mx; __syncthreads();
    for (int off = 128; off; off >>= 1) {
        if (tid < off) red[tid] = fmaxf(red[tid], red[tid + off]);
        __syncthreads();
    }
    mx = red[0]; __syncthreads();
    float sum = 0.f;
    for (int l = tid; l < n; l += 256) { float e = expf(row[l] - mx); row[l] = e; sum += e; }
    red[tid] = sum; __syncthreads();
    for (int off = 128; off; off >>= 1) {
        if (tid < off) red[tid] += red[tid + off];
        __syncthreads();
    }
    float inv = 1.f / red[0];
    for (int l = tid; l < T_; l += 256) row[l] = (l < n) ? row[l] * inv : 0.f;
}

__global__ void pack_wo_k(const float* __restrict__ wo, float* __restrict__ out) {
    long long i = (long long)blockIdx.x * 256 + threadIdx.x;  // d*2048 + h*128 + k
    if (i >= (long long)DIM_ * 2048) return;
    int d = (int)(i >> 11);
    int r = (int)(i & 2047);
    int h = r >> 7, k = r & 127;
    out[i] = wo[(long long)d * 2048 + k * NH_ + h];
}

__global__ void gate_k(const float* __restrict__ xn, const float* __restrict__ gw,
                       const float* __restrict__ gb, float* affOut,
                       int* __restrict__ cnt, int* __restrict__ tok,
                       float* __restrict__ wt) {
    int bt = blockIdx.x;
    __shared__ float xrow[DIM_];
    __shared__ float aff[NE_];
    int tid = threadIdx.x;
    for (int d = tid; d < DIM_; d += 256) xrow[d] = xn[(long long)bt * DIM_ + d];
    __syncthreads();
    int w = tid >> 5, lane = tid & 31;
    for (int e = w; e < NE_; e += 8) {
        float s = 0.f;
        const float* gr = gw + (long long)e * DIM_;
        for (int d = lane; d < DIM_; d += 32) s += xrow[d] * gr[d];
        for (int o = 16; o; o >>= 1) s += __shfl_xor_sync(0xffffffffu, s, o);
        if (lane == 0) aff[e] = 1.f / (1.f + expf(-s)) + gb[e];
    }
    __syncthreads();
    if (tid == 0) {
        if (affOut) for (int e = 0; e < NE_; e++) affOut[(long long)bt * NE_ + e] = aff[e];
        bool used[NE_] = {};
        float wv[TOPK_]; int wi[TOPK_]; float sum = 0.f;
        for (int k = 0; k < TOPK_; k++) {
            float best = -1e30f; int bi = 0;
            for (int e = 0; e < NE_; e++)
                if (!used[e] && aff[e] > best) { best = aff[e]; bi = e; }
            used[bi] = true; wv[k] = best; wi[k] = bi; sum += best;
        }
        for (int k = 0; k < TOPK_; k++) {
            int e = wi[k];
            int pos = atomicAdd(&cnt[e], 1);
            tok[e * CAP_ + pos] = bt;
            wt [e * CAP_ + pos] = wv[k] / sum;
        }
    }
}

__global__ void silumul_k(float4* __restrict__ a, const float4* __restrict__ b, long long n4) {
    long long i = (long long)blockIdx.x * 256 + threadIdx.x;
    if (i >= n4) return;
    float4 x = a[i], y = b[i];
    x.x *= y.x; x.y *= y.y; x.z *= y.z; x.w *= y.w;
    x.x = x.x / (1.f + expf(-x.x));
    x.y = x.y / (1.f + expf(-x.y));
    x.z = x.z / (1.f + expf(-x.z));
    x.w = x.w / (1.f + expf(-x.w));
    a[i] = x;
}

__global__ void silumul_routed_k(float4* __restrict__ a, const float4* __restrict__ b,
                                 const int* __restrict__ cnt) {
    long long i = (long long)blockIdx.x * 256 + threadIdx.x;   // NE*CAP*MOE/4
    long long el = i << 2;
    int e = (int)(el >> 21);                // CAP_*MOE_ = 2^21
    int ri = (int)((el >> 10) & (CAP_ - 1));
    if (ri >= cnt[e]) return;
    float4 x = a[i], y = b[i];
    x.x *= y.x; x.y *= y.y; x.z *= y.z; x.w *= y.w;
    x.x = x.x / (1.f + expf(-x.x));
    x.y = x.y / (1.f + expf(-x.y));
    x.z = x.z / (1.f + expf(-x.z));
    x.w = x.w / (1.f + expf(-x.w));
    a[i] = x;
}

// ---------------- host-side launch helpers ------------------------------------
template<int MODE>
static void gemm(const float* A, const float* B, float* C, int M, int N, int K,
                 int lda, int ldb, int ldc, float alpha, const float* res,
                 int nz, int zdiv,
                 long long a1, long long a2, long long b1, long long b2,
                 long long c1, long long c2,
                 const int* Mvec = nullptr, const int* aRows = nullptr,
                 const int* cRows = nullptr, const float* wRow = nullptr,
                 int cap = 0, int causal = 0, int causalAV = 0) {
    GemmP p;
    p.A = A; p.B = B; p.C = C; p.res = res;
    p.M = M; p.N = N; p.K = K; p.lda = lda; p.ldb = ldb; p.ldc = ldc;
    p.alpha = alpha;
    p.aO1 = a1; p.aO2 = a2; p.bO1 = b1; p.bO2 = b2; p.cO1 = c1; p.cO2 = c2;
    p.zdiv = zdiv; p.cap = cap;
    p.Mvec = Mvec; p.aRows = aRows; p.cRows = cRows; p.wRow = wRow;
    p.causal = causal; p.causalAV = causalAV;
    dim3 g((N + 127) / 128, (M + 127) / 128, nz);
    gemm_k<MODE><<<g, 256>>>(p);
}

extern "C" void kernel_launch(void* const* d_in, const int* in_sizes, int n_in,
                              void* d_out, int out_size) {
    const float* x      = (const float*)d_in[0];
    const float* attn_w = (const float*)d_in[3];
    const float* ffn_w  = (const float*)d_in[4];
    const float* gate_w = (const float*)d_in[5];
    const float* gate_b = (const float*)d_in[6];
    const float* w1s    = (const float*)d_in[7];
    const float* w2s    = (const float*)d_in[8];
    const float* w3s    = (const float*)d_in[9];
    const float* w1r    = (const float*)d_in[10];
    const float* w2r    = (const float*)d_in[11];
    const float* w3r    = (const float*)d_in[12];
    const float* wdkv   = (const float*)d_in[13];
    const float* wuk    = (const float*)d_in[14];
    const float* wuv    = (const float*)d_in[15];
    const float* wdq    = (const float*)d_in[16];
    const float* wuq    = (const float*)d_in[17];
    const float* wqr    = (const float*)d_in[18];
    const float* wkr    = (const float*)d_in[19];
    const float* wo     = (const float*)d_in[20];
    float* out = (float*)d_out;

    float *h, *ckv, *cq, *Q, *K, *V, *kr, *S, *O, *Wo, *x1, *xn, *a1, *a3, *h1, *h2, *wt;
    int *cnt, *tok;
    cudaGetSymbolAddress((void**)&h,   g_h);
    cudaGetSymbolAddress((void**)&ckv, g_ckv);
    cudaGetSymbolAddress((void**)&cq,  g_cq);
    cudaGetSymbolAddress((void**)&Q,   g_Q);
    cudaGetSymbolAddress((void**)&K,   g_K);
    cudaGetSymbolAddress((void**)&V,   g_V);
    cudaGetSymbolAddress((void**)&kr,  g_kr);
    cudaGetSymbolAddress((void**)&S,   g_S);
    cudaGetSymbolAddress((void**)&O,   g_O);
    cudaGetSymbolAddress((void**)&Wo,  g_Wo);
    cudaGetSymbolAddress((void**)&x1,  g_x1);
    cudaGetSymbolAddress((void**)&xn,  g_xn);
    cudaGetSymbolAddress((void**)&a1,  g_a1);
    cudaGetSymbolAddress((void**)&a3,  g_a3);
    cudaGetSymbolAddress((void**)&h1,  g_h1);
    cudaGetSymbolAddress((void**)&h2,  g_h2);
    cudaGetSymbolAddress((void**)&cnt, g_cnt);
    cudaGetSymbolAddress((void**)&tok, g_tok);
    cudaGetSymbolAddress((void**)&wt,  g_wt);

    // ---- attention ----
    rmsnorm_k<<<BT_, 256>>>(x, attn_w, h);
    gemm<1>(h, wdkv, ckv, BT_, DC_, DIM_, DIM_, DIM_, DC_, 1.f, nullptr, 1, 1, 0,0,0,0,0,0);
    gemm<1>(h, wdq,  cq,  BT_, DC_, DIM_, DIM_, DIM_, DC_, 1.f, nullptr, 1, 1, 0,0,0,0,0,0);
    gemm<1>(ckv, wuk, K,       BT_, DH_,  DC_, DC_, NH_*DC_, NH_*QKD_, 1.f, nullptr,
            NH_, NH_, 0,0, 0, DC_, 0, QKD_);
    gemm<1>(ckv, wuv, V,       BT_, DH_,  DC_, DC_, NH_*DC_, NH_*DH_,  1.f, nullptr,
            NH_, NH_, 0,0, 0, DC_, 0, DH_);
    gemm<1>(cq,  wuq, Q,       BT_, DH_,  DC_, DC_, NH_*DC_, NH_*QKD_, 1.f, nullptr,
            NH_, NH_, 0,0, 0, DC_, 0, QKD_);
    gemm<1>(cq,  wqr, Q + DH_, BT_, DRH_, DC_, DC_, NH_*DC_, NH_*QKD_, 1.f, nullptr,
            NH_, NH_, 0,0, 0, DC_, 0, QKD_);
    gemm<1>(h, wkr, kr, BT_, DRH_, DIM_, DIM_, DIM_, DRH_, 1.f, nullptr, 1, 1, 0,0,0,0,0,0);
    rope_q_k<<<BT_ * NH_, 32>>>(Q);
    rope_kr_k<<<BT_, 32>>>(kr, K);
    // logits (batched over b,h), scaled; causal block skip
    float scale = 1.0f / sqrtf((float)QKD_);
    gemm<1>(Q, K, S, T_, T_, QKD_, NH_*QKD_, NH_*QKD_, T_, scale, nullptr,
            B_*NH_, NH_,
            (long long)T_*NH_*QKD_, QKD_,
            (long long)T_*NH_*QKD_, QKD_,
            (long long)NH_*T_*T_, (long long)T_*T_,
            nullptr, nullptr, nullptr, nullptr, 0, /*causal=*/1);
    softmax_k<<<B_ * NH_ * T_, 256>>>(S);
    // out[l,k] = sum_t S[t,l] V[t,k]  (TN); skip K chunks with t < l (S==0 there)
    gemm<2>(S, V, O, T_, DH_, T_, T_, NH_*DH_, NH_*DH_, 1.f, nullptr,
            B_*NH_, NH_,
            (long long)NH_*T_*T_, (long long)T_*T_,
            (long long)T_*NH_*DH_, DH_,
            (long long)T_*NH_*DH_, DH_,
            nullptr, nullptr, nullptr, nullptr, 0, 0, /*causalAV=*/1);
    // attn projection + residual
    pack_wo_k<<<(DIM_*2048 + 255)/256, 256>>>(wo, Wo);
    gemm<1>(O, Wo, x1, BT_, DIM_, NH_*DH_, NH_*DH_, NH_*DH_, DIM_, 1.f, x,
            1, 1, 0,0,0,0,0,0);

    // ---- MoE ----
    rmsnorm_k<<<BT_, 256>>>(x1, ffn_w, xn);
    cudaMemsetAsync(cnt, 0, NE_ * sizeof(int));
    float* affOut = (out_size >= BT_*DIM_ + BT_*NE_) ? out + (long long)BT_*DIM_ : nullptr;
    gate_k<<<BT_, 256>>>(xn, gate_w, gate_b, affOut, cnt, tok, wt);
    // shared expert
    gemm<0>(xn, w1s, a1, BT_, MOESH_, DIM_, DIM_, MOESH_, MOESH_, 1.f, nullptr, 1,1,0,0,0,0,0,0);
    gemm<0>(xn, w3s, a3, BT_, MOESH_, DIM_, DIM_, MOESH_, MOESH_, 1.f, nullptr, 1,1,0,0,0,0,0,0);
    silumul_k<<<((BT_*MOESH_/4) + 255)/256, 256>>>((float4*)a1, (const float4*)a3,
                                                   (long long)BT_*MOESH_/4);
    gemm<0>(a1, w2s, out, BT_, DIM_, MOESH_, MOESH_, DIM_, DIM_, 1.f, x1, 1,1,0,0,0,0,0,0);
    // routed experts (top-4 only; gathered GEMMs with dynamic M, fused weighted scatter)
    gemm<0>(xn, w1r, h1, CAP_, MOE_, DIM_, DIM_, MOE_, MOE_, 1.f, nullptr,
            NE_, NE_, 0,0, 0, (long long)DIM_*MOE_, 0, (long long)CAP_*MOE_,
            cnt, tok, nullptr, nullptr, CAP_);
    gemm<0>(xn, w3r, h2, CAP_, MOE_, DIM_, DIM_, MOE_, MOE_, 1.f, nullptr,
            NE_, NE_, 0,0, 0, (long long)DIM_*MOE_, 0, (long long)CAP_*MOE_,
            cnt, tok, nullptr, nullptr, CAP_);
    silumul_routed_k<<<(((long long)NE_*CAP_*MOE_/4) + 255)/256, 256>>>(
        (float4*)h1, (const float4*)h2, cnt);
    gemm<0>(h1, w2r, out, CAP_, DIM_, MOE_, MOE_, DIM_, DIM_, 1.f, nullptr,
            NE_, NE_, 0, (long long)CAP_*MOE_, 0, (long long)MOE_*DIM_, 0, 0,
            cnt, nullptr, tok, wt, CAP_);
}